// round 1
// baseline (speedup 1.0000x reference)
#include <cuda_runtime.h>
#include <math.h>

// ---------------- problem constants ----------------
#define BB   2
#define TT   2048
#define DD   2048
#define NHH  16
#define HDD  128
#define RR   64
#define CQQ  1536
#define CKVV 512
#define BT   (BB*TT)       // 4096
#define DQK  192           // HD + R
#define DVV  128
#define HALFW 256          // WINDOW/2
#define RSCALE 0.07216878364870323f  // 1/sqrt(192)

// ---------------- scratch (device globals; no runtime alloc) ----------------
__device__ float g_qlat [(size_t)BT*CQQ];
__device__ float g_kvlat[(size_t)BT*CKVV];
__device__ float g_qc   [(size_t)BT*NHH*HDD];
__device__ float g_qr   [(size_t)BT*NHH*RR];
__device__ float g_kc   [(size_t)BT*NHH*HDD];
__device__ float g_vv   [(size_t)BT*NHH*HDD];
__device__ float g_kr   [(size_t)BT*NHH*RR];
__device__ float g_Q    [(size_t)BB*NHH*TT*DQK];
__device__ float g_K    [(size_t)BB*NHH*TT*DQK];
__device__ float g_V    [(size_t)BB*NHH*TT*DVV];
__device__ float g_alpha[BT];
__device__ float g_merged[(size_t)BT*NHH*HDD];

// ---------------- 128x128x8 fp32 SGEMM (M,N mult of 128; K mult of 8) -------
__global__ __launch_bounds__(256) void sgemm128(
    const float* __restrict__ A, const float* __restrict__ B,
    float* __restrict__ C, int M, int N, int K)
{
    __shared__ __align__(16) float As[8][128];
    __shared__ __align__(16) float Bs[8][128];
    int tid = threadIdx.x;
    int bx = blockIdx.x, by = blockIdx.y;
    int arow = tid >> 1;
    int acol = (tid & 1) << 2;
    int brow = tid >> 5;
    int bcol = (tid & 31) << 2;
    int tx = tid & 15, ty = tid >> 4;

    float acc[8][8];
#pragma unroll
    for (int i = 0; i < 8; i++)
#pragma unroll
        for (int j = 0; j < 8; j++) acc[i][j] = 0.f;

    const float* Aptr = A + (size_t)(by*128 + arow)*K + acol;
    const float* Bptr = B + (size_t)brow*N + bx*128 + bcol;

    for (int k0 = 0; k0 < K; k0 += 8) {
        float4 a4 = *(const float4*)(Aptr + k0);
        float4 b4 = *(const float4*)(Bptr + (size_t)k0*N);
        As[acol+0][arow] = a4.x; As[acol+1][arow] = a4.y;
        As[acol+2][arow] = a4.z; As[acol+3][arow] = a4.w;
        *(float4*)&Bs[brow][bcol] = b4;
        __syncthreads();
#pragma unroll
        for (int kk = 0; kk < 8; kk++) {
            float4 a0 = *(const float4*)&As[kk][ty*4];
            float4 a1 = *(const float4*)&As[kk][64 + ty*4];
            float4 b0 = *(const float4*)&Bs[kk][tx*4];
            float4 b1 = *(const float4*)&Bs[kk][64 + tx*4];
            float ra[8] = {a0.x,a0.y,a0.z,a0.w,a1.x,a1.y,a1.z,a1.w};
            float rb[8] = {b0.x,b0.y,b0.z,b0.w,b1.x,b1.y,b1.z,b1.w};
#pragma unroll
            for (int i = 0; i < 8; i++)
#pragma unroll
                for (int j = 0; j < 8; j++)
                    acc[i][j] += ra[i]*rb[j];
        }
        __syncthreads();
    }
#pragma unroll
    for (int i = 0; i < 8; i++) {
        int row = by*128 + ((i < 4) ? (ty*4 + i) : (64 + ty*4 + i - 4));
#pragma unroll
        for (int jc = 0; jc < 2; jc++) {
            float4 v = make_float4(acc[i][jc*4+0], acc[i][jc*4+1],
                                   acc[i][jc*4+2], acc[i][jc*4+3]);
            *(float4*)&C[(size_t)row*N + bx*128 + jc*64 + tx*4] = v;
        }
    }
}

// ---------------- RMSNorm (in place, 1 block per row) ----------------
__global__ __launch_bounds__(256) void rmsnorm_kernel(
    float* __restrict__ x, const float* __restrict__ w, int n)
{
    float* row = x + (size_t)blockIdx.x * n;
    float ss = 0.f;
    for (int i = threadIdx.x; i < n; i += 256) { float v = row[i]; ss += v*v; }
    __shared__ float sh[8];
    __shared__ float tot;
    int lane = threadIdx.x & 31, wp = threadIdx.x >> 5;
#pragma unroll
    for (int o = 16; o; o >>= 1) ss += __shfl_xor_sync(0xffffffffu, ss, o);
    if (lane == 0) sh[wp] = ss;
    __syncthreads();
    if (threadIdx.x == 0) {
        float s = 0.f;
        for (int i = 0; i < 8; i++) s += sh[i];
        tot = rsqrtf(s / n + 1e-6f);
    }
    __syncthreads();
    float rs = tot;
    for (int i = threadIdx.x; i < n; i += 256) row[i] = row[i] * rs * w[i];
}

// ---------------- gate alpha = sigmoid(x @ Wgate + b) ----------------
__global__ __launch_bounds__(256) void alpha_kernel(
    const float* __restrict__ x, const float* __restrict__ wg,
    const float* __restrict__ bg, float* __restrict__ alpha,
    float* __restrict__ out_alpha)
{
    const float* row = x + (size_t)blockIdx.x * DD;
    float s = 0.f;
    for (int i = threadIdx.x; i < DD; i += 256) s += row[i] * wg[i];
    __shared__ float sh[8];
    int lane = threadIdx.x & 31, wp = threadIdx.x >> 5;
#pragma unroll
    for (int o = 16; o; o >>= 1) s += __shfl_xor_sync(0xffffffffu, s, o);
    if (lane == 0) sh[wp] = s;
    __syncthreads();
    if (threadIdx.x == 0) {
        float t = 0.f;
        for (int i = 0; i < 8; i++) t += sh[i];
        float z = t + bg[0];
        float a = 1.f / (1.f + expf(-z));
        alpha[blockIdx.x] = a;
        if (out_alpha) out_alpha[blockIdx.x] = a;
    }
}

// ---------------- assemble Q/K/V with EPE-RoPE ----------------
// grid = BT*NH blocks, 128 threads. Q,K: (b*NH+h, t, 192), V: (b*NH+h, t, 128)
__global__ __launch_bounds__(128) void assemble_kernel(
    const float* __restrict__ qc, const float* __restrict__ qr,
    const float* __restrict__ kc, const float* __restrict__ kr,
    const float* __restrict__ vv, const float* __restrict__ unc,
    float* __restrict__ Q, float* __restrict__ K, float* __restrict__ V)
{
    int idx = blockIdx.x;
    int h  = idx % NHH;
    int bt = idx / NHH;
    int t  = bt % TT;
    int b  = bt / TT;
    __shared__ float cs[32], sn[32];
    int d = threadIdx.x;
    if (d < 32) {
        float u = unc[bt];
        u = fminf(fmaxf(u, 0.f), 1.f);
        float scale = 0.5f + 1.5f * u;
        float fi = (float)d / 32.0f;                 // i*2/R
        float theta = expf(-fi * logf(500000.0f));   // ROPE_BASE^{-fi}
        float fr = (float)t * theta * scale;
        cs[d] = cosf(fr);
        sn[d] = sinf(fr);
    }
    __syncthreads();
    size_t qkrow = ((size_t)(b*NHH + h))*TT + t;
    Q[qkrow*DQK + d] = qc[(size_t)bt*2048 + h*128 + d];
    K[qkrow*DQK + d] = kc[(size_t)bt*2048 + h*128 + d];
    V[qkrow*DVV + d] = vv[(size_t)bt*2048 + h*128 + d];
    if (d < 64) {
        const float* qrp = qr + (size_t)bt*1024 + h*64;
        const float* krp = kr + (size_t)bt*1024 + h*64;
        float qv, kv;
        if (d < 32) {
            float c = cs[d], s = sn[d];
            qv = qrp[d]*c - qrp[d+32]*s;
            kv = krp[d]*c - krp[d+32]*s;
        } else {
            int j = d - 32;
            float c = cs[j], s = sn[j];
            qv = qrp[j+32]*c + qrp[j]*s;
            kv = krp[j+32]*c + krp[j]*s;
        }
        Q[qkrow*DQK + 128 + d] = qv;
        K[qkrow*DQK + 128 + d] = kv;
    }
}

// ---------------- fused dual attention (bidir + AR window) ----------------
// grid = B*NH*(T/8) blocks, 256 threads: warp = 1 query, lane = 1 key of tile.
__global__ __launch_bounds__(256) void attn_kernel(
    const float* __restrict__ Q, const float* __restrict__ K,
    const float* __restrict__ V, const float* __restrict__ alpha,
    float* __restrict__ merged)
{
    __shared__ __align__(16) float Ks[32][196];  // pad: stride%32==4 -> conflict-free LDS.128
    __shared__ __align__(16) float Vs[32][128];
    __shared__ __align__(16) float Qs[8][192];

    int bh = blockIdx.x >> 8;           // / (T/8)
    int qt = (blockIdx.x & 255) << 3;
    int tid = threadIdx.x, warp = tid >> 5, lane = tid & 31;
    int b = bh >> 4, h = bh & 15;

    for (int i = tid; i < 8*192; i += 256) {
        int w = i / 192, d = i % 192;
        Qs[w][d] = Q[((size_t)bh*TT + qt + w)*DQK + d];
    }
    __syncthreads();

    int q = qt + warp;
    int winlo = ((q >> 8) << 8) - HALFW;
    if (winlo < 0) winlo = 0;

    float m = -1e30f, l = 0.f, lw = 0.f;
    float accb[4] = {0,0,0,0}, accw[4] = {0,0,0,0};

    for (int kt = 0; kt < TT; kt += 32) {
        for (int i = tid; i < 32*192; i += 256) {
            int r = i / 192, c = i % 192;
            Ks[r][c] = K[((size_t)bh*TT + kt + r)*DQK + c];
        }
        for (int i = tid; i < 32*128; i += 256) {
            int r = i >> 7, c = i & 127;
            Vs[r][c] = V[((size_t)bh*TT + kt + r)*DVV + c];
        }
        __syncthreads();

        // score for key = kt + lane (shared by both attention streams)
        float s = 0.f;
        const float4* kr4 = (const float4*)&Ks[lane][0];
        const float4* qr4 = (const float4*)&Qs[warp][0];
#pragma unroll
        for (int d4 = 0; d4 < 48; d4++) {
            float4 kv = kr4[d4], qv = qr4[d4];
            s += qv.x*kv.x; s += qv.y*kv.y; s += qv.z*kv.z; s += qv.w*kv.w;
        }
        s *= RSCALE;

        float tmax = s;
#pragma unroll
        for (int o = 16; o; o >>= 1)
            tmax = fmaxf(tmax, __shfl_xor_sync(0xffffffffu, tmax, o));
        float mnew = fmaxf(m, tmax);
        float corr = __expf(m - mnew);
        l *= corr; lw *= corr;
#pragma unroll
        for (int i = 0; i < 4; i++) { accb[i] *= corr; accw[i] *= corr; }

        float p = __expf(s - mnew);
        int key = kt + lane;
        bool inwin = (key >= winlo) && (key <= q);
        float pw = inwin ? p : 0.f;
        float psum = p, pwsum = pw;
#pragma unroll
        for (int o = 16; o; o >>= 1) {
            psum  += __shfl_xor_sync(0xffffffffu, psum,  o);
            pwsum += __shfl_xor_sync(0xffffffffu, pwsum, o);
        }
        l += psum; lw += pwsum;
        m = mnew;

        unsigned wm = __ballot_sync(0xffffffffu, inwin);
#pragma unroll 4
        for (int j = 0; j < 32; j++) {
            float pj = __shfl_sync(0xffffffffu, p, j);
            float4 v = *(const float4*)&Vs[j][lane*4];
            accb[0] += pj*v.x; accb[1] += pj*v.y;
            accb[2] += pj*v.z; accb[3] += pj*v.w;
            if ((wm >> j) & 1u) {
                float pwj = __shfl_sync(0xffffffffu, pw, j);
                accw[0] += pwj*v.x; accw[1] += pwj*v.y;
                accw[2] += pwj*v.z; accw[3] += pwj*v.w;
            }
        }
        __syncthreads();
    }

    float a  = alpha[(size_t)b*TT + q];
    float il = 1.f/l, ilw = 1.f/lw;
    float4 outv;
    outv.x = a*accb[0]*il + (1.f-a)*accw[0]*ilw;
    outv.y = a*accb[1]*il + (1.f-a)*accw[1]*ilw;
    outv.z = a*accb[2]*il + (1.f-a)*accw[2]*ilw;
    outv.w = a*accb[3]*il + (1.f-a)*accw[3]*ilw;
    *(float4*)&merged[((size_t)b*TT + q)*2048 + h*128 + lane*4] = outv;
}

// ---------------- launcher ----------------
extern "C" void kernel_launch(void* const* d_in, const int* in_sizes, int n_in,
                              void* d_out, int out_size)
{
    (void)in_sizes; (void)n_in;
    const float* x        = (const float*)d_in[0];
    const float* unc      = (const float*)d_in[1];
    const float* Wq_down  = (const float*)d_in[2];
    const float* q_norm_w = (const float*)d_in[3];
    const float* Wq_up    = (const float*)d_in[4];
    const float* Wq_rope  = (const float*)d_in[5];
    const float* Wkv_down = (const float*)d_in[6];
    const float* kv_norm_w= (const float*)d_in[7];
    const float* Wk_up    = (const float*)d_in[8];
    const float* Wv_up    = (const float*)d_in[9];
    const float* Wk_rope  = (const float*)d_in[10];
    const float* Wout     = (const float*)d_in[11];
    const float* Wgate    = (const float*)d_in[12];
    const float* bgate    = (const float*)d_in[13];
    float* out = (float*)d_out;

    float *qlat, *kvlat, *qc, *qr, *kc, *vv, *kr, *Qb, *Kb, *Vb, *al, *mg;
    cudaGetSymbolAddress((void**)&qlat,  g_qlat);
    cudaGetSymbolAddress((void**)&kvlat, g_kvlat);
    cudaGetSymbolAddress((void**)&qc,    g_qc);
    cudaGetSymbolAddress((void**)&qr,    g_qr);
    cudaGetSymbolAddress((void**)&kc,    g_kc);
    cudaGetSymbolAddress((void**)&vv,    g_vv);
    cudaGetSymbolAddress((void**)&kr,    g_kr);
    cudaGetSymbolAddress((void**)&Qb,    g_Q);
    cudaGetSymbolAddress((void**)&Kb,    g_K);
    cudaGetSymbolAddress((void**)&Vb,    g_V);
    cudaGetSymbolAddress((void**)&al,    g_alpha);
    cudaGetSymbolAddress((void**)&mg,    g_merged);

    // latent projections + norms
    sgemm128<<<dim3(CQQ/128,  BT/128), 256>>>(x, Wq_down,  qlat,  BT, CQQ,  DD);
    rmsnorm_kernel<<<BT, 256>>>(qlat, q_norm_w, CQQ);
    sgemm128<<<dim3(CKVV/128, BT/128), 256>>>(x, Wkv_down, kvlat, BT, CKVV, DD);
    rmsnorm_kernel<<<BT, 256>>>(kvlat, kv_norm_w, CKVV);

    // up projections
    sgemm128<<<dim3(2048/128, BT/128), 256>>>(qlat,  Wq_up,   qc, BT, 2048, CQQ);
    sgemm128<<<dim3(1024/128, BT/128), 256>>>(qlat,  Wq_rope, qr, BT, 1024, CQQ);
    sgemm128<<<dim3(2048/128, BT/128), 256>>>(kvlat, Wk_up,   kc, BT, 2048, CKVV);
    sgemm128<<<dim3(2048/128, BT/128), 256>>>(kvlat, Wv_up,   vv, BT, 2048, CKVV);
    sgemm128<<<dim3(1024/128, BT/128), 256>>>(x,     Wk_rope, kr, BT, 1024, DD);

    // gate (also writes alpha output if harness expects it)
    float* out_alpha = (out_size >= BB*TT*DD + BB*TT) ? (out + (size_t)BB*TT*DD)
                                                      : nullptr;
    alpha_kernel<<<BT, 256>>>(x, Wgate, bgate, al, out_alpha);

    // build Q/K/V (rope + concat + transpose)
    assemble_kernel<<<BT*NHH, 128>>>(qc, qr, kc, kr, vv, unc, Qb, Kb, Vb);

    // fused dual attention -> merged (b, t, nh*hd)
    attn_kernel<<<BB*NHH*(TT/8), 256>>>(Qb, Kb, Vb, al, mg);

    // output projection
    sgemm128<<<dim3(DD/128, BT/128), 256>>>(mg, Wout, out, BT, DD, 2048);
}

// round 2
// speedup vs baseline: 1.2076x; 1.2076x over previous
#include <cuda_runtime.h>
#include <cuda_bf16.h>
#include <math.h>
#include <stdint.h>

// ---------------- problem constants ----------------
#define BB   2
#define TT   2048
#define DD   2048
#define NHH  16
#define HDD  128
#define RR   64
#define CQQ  1536
#define CKVV 512
#define BT   (BB*TT)       // 4096
#define DQK  192           // HD + R
#define DVV  128
#define HALFW 256          // WINDOW/2
#define RSCALE 0.07216878364870323f  // 1/sqrt(192)

typedef __nv_bfloat16 bf16;

// ---------------- scratch (device globals; no runtime alloc) ----------------
__device__ float g_qlat [(size_t)BT*CQQ];      // pre-norm fp32
__device__ float g_kvlat[(size_t)BT*CKVV];
__device__ float g_qc   [(size_t)BT*NHH*HDD];
__device__ float g_qr   [(size_t)BT*NHH*RR];
__device__ float g_kc   [(size_t)BT*NHH*HDD];
__device__ float g_vv   [(size_t)BT*NHH*HDD];
__device__ float g_kr   [(size_t)BT*NHH*RR];
__device__ float g_Q    [(size_t)BB*NHH*TT*DQK];
__device__ float g_K    [(size_t)BB*NHH*TT*DQK];
__device__ float g_V    [(size_t)BB*NHH*TT*DVV];
__device__ float g_alpha[BT];

// bf16 split buffers (hi/lo)
__device__ bf16 g_xh [(size_t)BT*DD],    g_xl [(size_t)BT*DD];
__device__ bf16 g_qlh[(size_t)BT*CQQ],   g_qll[(size_t)BT*CQQ];
__device__ bf16 g_kvh[(size_t)BT*CKVV],  g_kvl[(size_t)BT*CKVV];
__device__ bf16 g_mgh[(size_t)BT*NHH*HDD], g_mgl[(size_t)BT*NHH*HDD];
// weight splits
__device__ bf16 g_wqd_h[(size_t)DD*CQQ],     g_wqd_l[(size_t)DD*CQQ];
__device__ bf16 g_wqu_h[(size_t)CQQ*2048],   g_wqu_l[(size_t)CQQ*2048];
__device__ bf16 g_wqr_h[(size_t)CQQ*1024],   g_wqr_l[(size_t)CQQ*1024];
__device__ bf16 g_wkd_h[(size_t)DD*CKVV],    g_wkd_l[(size_t)DD*CKVV];
__device__ bf16 g_wku_h[(size_t)CKVV*2048],  g_wku_l[(size_t)CKVV*2048];
__device__ bf16 g_wvu_h[(size_t)CKVV*2048],  g_wvu_l[(size_t)CKVV*2048];
__device__ bf16 g_wkr_h[(size_t)DD*1024],    g_wkr_l[(size_t)DD*1024];
__device__ bf16 g_wo_h [(size_t)2048*DD],    g_wo_l [(size_t)2048*DD];

// ---------------- ptx helpers ----------------
__device__ __forceinline__ void ldsm_x4(uint32_t &r0, uint32_t &r1,
                                        uint32_t &r2, uint32_t &r3,
                                        const void* p) {
    uint32_t a = (uint32_t)__cvta_generic_to_shared(p);
    asm volatile("ldmatrix.sync.aligned.m8n8.x4.shared.b16 {%0,%1,%2,%3}, [%4];"
                 : "=r"(r0), "=r"(r1), "=r"(r2), "=r"(r3) : "r"(a));
}
__device__ __forceinline__ void ldsm_x2t(uint32_t &r0, uint32_t &r1,
                                         const void* p) {
    uint32_t a = (uint32_t)__cvta_generic_to_shared(p);
    asm volatile("ldmatrix.sync.aligned.m8n8.x2.trans.shared.b16 {%0,%1}, [%2];"
                 : "=r"(r0), "=r"(r1) : "r"(a));
}
__device__ __forceinline__ void mma_bf16(float* c, const uint32_t* a,
                                         const uint32_t* b) {
    asm volatile(
        "mma.sync.aligned.m16n8k16.row.col.f32.bf16.bf16.f32 "
        "{%0,%1,%2,%3}, {%4,%5,%6,%7}, {%8,%9}, {%0,%1,%2,%3};"
        : "+f"(c[0]), "+f"(c[1]), "+f"(c[2]), "+f"(c[3])
        : "r"(a[0]), "r"(a[1]), "r"(a[2]), "r"(a[3]), "r"(b[0]), "r"(b[1]));
}

// ---------------- split fp32 -> (hi, lo) bf16 ----------------
__global__ __launch_bounds__(256) void split_kernel(
    const float* __restrict__ s, bf16* __restrict__ h,
    bf16* __restrict__ l, int n)
{
    int i = (blockIdx.x * 256 + threadIdx.x) * 4;
    if (i >= n) return;
    float4 v = *(const float4*)(s + i);
    bf16 h0 = __float2bfloat16(v.x), h1 = __float2bfloat16(v.y);
    bf16 h2 = __float2bfloat16(v.z), h3 = __float2bfloat16(v.w);
    bf16 l0 = __float2bfloat16(v.x - __bfloat162float(h0));
    bf16 l1 = __float2bfloat16(v.y - __bfloat162float(h1));
    bf16 l2 = __float2bfloat16(v.z - __bfloat162float(h2));
    bf16 l3 = __float2bfloat16(v.w - __bfloat162float(h3));
    *(__nv_bfloat162*)(h + i)     = __nv_bfloat162(h0, h1);
    *(__nv_bfloat162*)(h + i + 2) = __nv_bfloat162(h2, h3);
    *(__nv_bfloat162*)(l + i)     = __nv_bfloat162(l0, l1);
    *(__nv_bfloat162*)(l + i + 2) = __nv_bfloat162(l2, l3);
}

// ---------------- split-bf16 tensor-core GEMM (fp32-class accuracy) --------
// C[M,N] = A[M,K] @ B[K,N], all dims mult of 128/128/32.
// block: 256 thr, tile 128x128x32; warp 64x32; 3 mma chains (hh, hl, lh).
__global__ __launch_bounds__(256) void gemm_split(
    const bf16* __restrict__ Ah, const bf16* __restrict__ Al,
    const bf16* __restrict__ Bh, const bf16* __restrict__ Bl,
    float* __restrict__ C, int M, int N, int K)
{
    __shared__ __align__(16) bf16 sAh[128*40];
    __shared__ __align__(16) bf16 sAl[128*40];
    __shared__ __align__(16) bf16 sBh[32*136];
    __shared__ __align__(16) bf16 sBl[32*136];

    int tid = threadIdx.x;
    int bm = blockIdx.y, bn = blockIdx.x;
    int warp = tid >> 5, lane = tid & 31;
    int wm = warp >> 2, wn = warp & 3;

    float acc[4][4][4];
#pragma unroll
    for (int a = 0; a < 4; a++)
#pragma unroll
        for (int b = 0; b < 4; b++)
#pragma unroll
            for (int c = 0; c < 4; c++) acc[a][b][c] = 0.f;

    for (int k0 = 0; k0 < K; k0 += 32) {
        // load A tiles (128x32) hi+lo
#pragma unroll
        for (int i = 0; i < 2; i++) {
            int v = tid + i * 256;
            int row = v >> 2, c = (v & 3) * 8;
            size_t g = (size_t)(bm * 128 + row) * K + k0 + c;
            *(uint4*)&sAh[row * 40 + c] = *(const uint4*)(Ah + g);
            *(uint4*)&sAl[row * 40 + c] = *(const uint4*)(Al + g);
        }
        // load B tiles (32x128) hi+lo
#pragma unroll
        for (int i = 0; i < 2; i++) {
            int v = tid + i * 256;
            int row = v >> 4, c = (v & 15) * 8;
            size_t g = (size_t)(k0 + row) * N + bn * 128 + c;
            *(uint4*)&sBh[row * 136 + c] = *(const uint4*)(Bh + g);
            *(uint4*)&sBl[row * 136 + c] = *(const uint4*)(Bl + g);
        }
        __syncthreads();

#pragma unroll
        for (int kh = 0; kh < 2; kh++) {
            uint32_t bh[4][2], bl[4][2];
#pragma unroll
            for (int nt = 0; nt < 4; nt++) {
                int brow = kh * 16 + (lane & 15);
                int bcol = wn * 32 + nt * 8;
                ldsm_x2t(bh[nt][0], bh[nt][1], &sBh[brow * 136 + bcol]);
                ldsm_x2t(bl[nt][0], bl[nt][1], &sBl[brow * 136 + bcol]);
            }
#pragma unroll
            for (int mt = 0; mt < 4; mt++) {
                int arow = wm * 64 + mt * 16 + (lane & 15);
                int acol = kh * 16 + (lane >> 4) * 8;
                uint32_t ah[4], al[4];
                ldsm_x4(ah[0], ah[1], ah[2], ah[3], &sAh[arow * 40 + acol]);
                ldsm_x4(al[0], al[1], al[2], al[3], &sAl[arow * 40 + acol]);
#pragma unroll
                for (int nt = 0; nt < 4; nt++) {
                    mma_bf16(acc[mt][nt], ah, bh[nt]);
                    mma_bf16(acc[mt][nt], ah, bl[nt]);
                    mma_bf16(acc[mt][nt], al, bh[nt]);
                }
            }
        }
        __syncthreads();
    }

    // epilogue
#pragma unroll
    for (int mt = 0; mt < 4; mt++) {
#pragma unroll
        for (int nt = 0; nt < 4; nt++) {
            int r0 = bm * 128 + wm * 64 + mt * 16 + (lane >> 2);
            int c0 = bn * 128 + wn * 32 + nt * 8 + (lane & 3) * 2;
            *(float2*)&C[(size_t)r0 * N + c0] =
                make_float2(acc[mt][nt][0], acc[mt][nt][1]);
            *(float2*)&C[(size_t)(r0 + 8) * N + c0] =
                make_float2(acc[mt][nt][2], acc[mt][nt][3]);
        }
    }
}

// ---------------- RMSNorm -> split bf16 outputs ----------------
__global__ __launch_bounds__(256) void rmsnorm_split_kernel(
    const float* __restrict__ x, const float* __restrict__ w,
    bf16* __restrict__ hi, bf16* __restrict__ lo, int n)
{
    const float* row = x + (size_t)blockIdx.x * n;
    float ss = 0.f;
    for (int i = threadIdx.x; i < n; i += 256) { float v = row[i]; ss += v*v; }
    __shared__ float sh[8];
    __shared__ float tot;
    int lane = threadIdx.x & 31, wp = threadIdx.x >> 5;
#pragma unroll
    for (int o = 16; o; o >>= 1) ss += __shfl_xor_sync(0xffffffffu, ss, o);
    if (lane == 0) sh[wp] = ss;
    __syncthreads();
    if (threadIdx.x == 0) {
        float s = 0.f;
        for (int i = 0; i < 8; i++) s += sh[i];
        tot = rsqrtf(s / n + 1e-6f);
    }
    __syncthreads();
    float rs = tot;
    bf16* hrow = hi + (size_t)blockIdx.x * n;
    bf16* lrow = lo + (size_t)blockIdx.x * n;
    for (int i = threadIdx.x; i < n; i += 256) {
        float y = row[i] * rs * w[i];
        bf16 h = __float2bfloat16(y);
        hrow[i] = h;
        lrow[i] = __float2bfloat16(y - __bfloat162float(h));
    }
}

// ---------------- gate alpha = sigmoid(x @ Wgate + b) ----------------
__global__ __launch_bounds__(256) void alpha_kernel(
    const float* __restrict__ x, const float* __restrict__ wg,
    const float* __restrict__ bg, float* __restrict__ alpha,
    float* __restrict__ out_alpha)
{
    const float* row = x + (size_t)blockIdx.x * DD;
    float s = 0.f;
    for (int i = threadIdx.x; i < DD; i += 256) s += row[i] * wg[i];
    __shared__ float sh[8];
    int lane = threadIdx.x & 31, wp = threadIdx.x >> 5;
#pragma unroll
    for (int o = 16; o; o >>= 1) s += __shfl_xor_sync(0xffffffffu, s, o);
    if (lane == 0) sh[wp] = s;
    __syncthreads();
    if (threadIdx.x == 0) {
        float t = 0.f;
        for (int i = 0; i < 8; i++) t += sh[i];
        float z = t + bg[0];
        float a = 1.f / (1.f + expf(-z));
        alpha[blockIdx.x] = a;
        if (out_alpha) out_alpha[blockIdx.x] = a;
    }
}

// ---------------- assemble Q/K/V with EPE-RoPE ----------------
__global__ __launch_bounds__(128) void assemble_kernel(
    const float* __restrict__ qc, const float* __restrict__ qr,
    const float* __restrict__ kc, const float* __restrict__ kr,
    const float* __restrict__ vv, const float* __restrict__ unc,
    float* __restrict__ Q, float* __restrict__ K, float* __restrict__ V)
{
    int idx = blockIdx.x;
    int h  = idx % NHH;
    int bt = idx / NHH;
    int t  = bt % TT;
    int b  = bt / TT;
    __shared__ float cs[32], sn[32];
    int d = threadIdx.x;
    if (d < 32) {
        float u = unc[bt];
        u = fminf(fmaxf(u, 0.f), 1.f);
        float scale = 0.5f + 1.5f * u;
        float fi = (float)d / 32.0f;
        float theta = expf(-fi * logf(500000.0f));
        float fr = (float)t * theta * scale;
        cs[d] = cosf(fr);
        sn[d] = sinf(fr);
    }
    __syncthreads();
    size_t qkrow = ((size_t)(b*NHH + h))*TT + t;
    Q[qkrow*DQK + d] = qc[(size_t)bt*2048 + h*128 + d];
    K[qkrow*DQK + d] = kc[(size_t)bt*2048 + h*128 + d];
    V[qkrow*DVV + d] = vv[(size_t)bt*2048 + h*128 + d];
    if (d < 64) {
        const float* qrp = qr + (size_t)bt*1024 + h*64;
        const float* krp = kr + (size_t)bt*1024 + h*64;
        float qv, kv;
        if (d < 32) {
            float c = cs[d], s = sn[d];
            qv = qrp[d]*c - qrp[d+32]*s;
            kv = krp[d]*c - krp[d+32]*s;
        } else {
            int j = d - 32;
            float c = cs[j], s = sn[j];
            qv = qrp[j+32]*c + qrp[j]*s;
            kv = krp[j+32]*c + krp[j]*s;
        }
        Q[qkrow*DQK + 128 + d] = qv;
        K[qkrow*DQK + 128 + d] = kv;
    }
}

// ---------------- fused dual attention (bidir + AR window) ----------------
__global__ __launch_bounds__(256) void attn_kernel(
    const float* __restrict__ Q, const float* __restrict__ K,
    const float* __restrict__ V, const float* __restrict__ alpha,
    bf16* __restrict__ mgh, bf16* __restrict__ mgl)
{
    __shared__ __align__(16) float Ks[32][196];
    __shared__ __align__(16) float Vs[32][128];
    __shared__ __align__(16) float Qs[8][192];

    int bh = blockIdx.x >> 8;
    int qt = (blockIdx.x & 255) << 3;
    int tid = threadIdx.x, warp = tid >> 5, lane = tid & 31;
    int b = bh >> 4, h = bh & 15;

    for (int i = tid; i < 8*192; i += 256) {
        int w = i / 192, d = i % 192;
        Qs[w][d] = Q[((size_t)bh*TT + qt + w)*DQK + d];
    }
    __syncthreads();

    int q = qt + warp;
    int winlo = ((q >> 8) << 8) - HALFW;
    if (winlo < 0) winlo = 0;

    float m = -1e30f, l = 0.f, lw = 0.f;
    float accb[4] = {0,0,0,0}, accw[4] = {0,0,0,0};

    for (int kt = 0; kt < TT; kt += 32) {
        for (int i = tid; i < 32*192; i += 256) {
            int r = i / 192, c = i % 192;
            Ks[r][c] = K[((size_t)bh*TT + kt + r)*DQK + c];
        }
        for (int i = tid; i < 32*128; i += 256) {
            int r = i >> 7, c = i & 127;
            Vs[r][c] = V[((size_t)bh*TT + kt + r)*DVV + c];
        }
        __syncthreads();

        float s = 0.f;
        const float4* kr4 = (const float4*)&Ks[lane][0];
        const float4* qr4 = (const float4*)&Qs[warp][0];
#pragma unroll
        for (int d4 = 0; d4 < 48; d4++) {
            float4 kv = kr4[d4], qv = qr4[d4];
            s += qv.x*kv.x; s += qv.y*kv.y; s += qv.z*kv.z; s += qv.w*kv.w;
        }
        s *= RSCALE;

        float tmax = s;
#pragma unroll
        for (int o = 16; o; o >>= 1)
            tmax = fmaxf(tmax, __shfl_xor_sync(0xffffffffu, tmax, o));
        float mnew = fmaxf(m, tmax);
        float corr = __expf(m - mnew);
        l *= corr; lw *= corr;
#pragma unroll
        for (int i = 0; i < 4; i++) { accb[i] *= corr; accw[i] *= corr; }

        float p = __expf(s - mnew);
        int key = kt + lane;
        bool inwin = (key >= winlo) && (key <= q);
        float pw = inwin ? p : 0.f;
        float psum = p, pwsum = pw;
#pragma unroll
        for (int o = 16; o; o >>= 1) {
            psum  += __shfl_xor_sync(0xffffffffu, psum,  o);
            pwsum += __shfl_xor_sync(0xffffffffu, pwsum, o);
        }
        l += psum; lw += pwsum;
        m = mnew;

        unsigned wm = __ballot_sync(0xffffffffu, inwin);
#pragma unroll 4
        for (int j = 0; j < 32; j++) {
            float pj = __shfl_sync(0xffffffffu, p, j);
            float4 v = *(const float4*)&Vs[j][lane*4];
            accb[0] += pj*v.x; accb[1] += pj*v.y;
            accb[2] += pj*v.z; accb[3] += pj*v.w;
            if ((wm >> j) & 1u) {
                float pwj = __shfl_sync(0xffffffffu, pw, j);
                accw[0] += pwj*v.x; accw[1] += pwj*v.y;
                accw[2] += pwj*v.z; accw[3] += pwj*v.w;
            }
        }
        __syncthreads();
    }

    float a  = alpha[(size_t)b*TT + q];
    float il = 1.f/l, ilw = 1.f/lw;
    float ov[4];
    ov[0] = a*accb[0]*il + (1.f-a)*accw[0]*ilw;
    ov[1] = a*accb[1]*il + (1.f-a)*accw[1]*ilw;
    ov[2] = a*accb[2]*il + (1.f-a)*accw[2]*ilw;
    ov[3] = a*accb[3]*il + (1.f-a)*accw[3]*ilw;

    size_t o = ((size_t)b*TT + q)*2048 + h*128 + lane*4;
    bf16 h0 = __float2bfloat16(ov[0]), h1 = __float2bfloat16(ov[1]);
    bf16 h2 = __float2bfloat16(ov[2]), h3 = __float2bfloat16(ov[3]);
    *(__nv_bfloat162*)(mgh + o)     = __nv_bfloat162(h0, h1);
    *(__nv_bfloat162*)(mgh + o + 2) = __nv_bfloat162(h2, h3);
    bf16 l0 = __float2bfloat16(ov[0] - __bfloat162float(h0));
    bf16 l1 = __float2bfloat16(ov[1] - __bfloat162float(h1));
    bf16 l2 = __float2bfloat16(ov[2] - __bfloat162float(h2));
    bf16 l3 = __float2bfloat16(ov[3] - __bfloat162float(h3));
    *(__nv_bfloat162*)(mgl + o)     = __nv_bfloat162(l0, l1);
    *(__nv_bfloat162*)(mgl + o + 2) = __nv_bfloat162(l2, l3);
}

// ---------------- launcher ----------------
extern "C" void kernel_launch(void* const* d_in, const int* in_sizes, int n_in,
                              void* d_out, int out_size)
{
    (void)in_sizes; (void)n_in;
    const float* x        = (const float*)d_in[0];
    const float* unc      = (const float*)d_in[1];
    const float* Wq_down  = (const float*)d_in[2];
    const float* q_norm_w = (const float*)d_in[3];
    const float* Wq_up    = (const float*)d_in[4];
    const float* Wq_rope  = (const float*)d_in[5];
    const float* Wkv_down = (const float*)d_in[6];
    const float* kv_norm_w= (const float*)d_in[7];
    const float* Wk_up    = (const float*)d_in[8];
    const float* Wv_up    = (const float*)d_in[9];
    const float* Wk_rope  = (const float*)d_in[10];
    const float* Wout     = (const float*)d_in[11];
    const float* Wgate    = (const float*)d_in[12];
    const float* bgate    = (const float*)d_in[13];
    float* out = (float*)d_out;

    float *qlat, *kvlat, *qc, *qr, *kc, *vv, *kr, *Qb, *Kb, *Vb, *al;
    bf16 *xh,*xl,*qlh,*qll,*kvh,*kvl,*mgh,*mgl;
    bf16 *wqdh,*wqdl,*wquh,*wqul,*wqrh,*wqrl,*wkdh,*wkdl;
    bf16 *wkuh,*wkul,*wvuh,*wvul,*wkrh,*wkrl,*woh,*wol;
    cudaGetSymbolAddress((void**)&qlat,  g_qlat);
    cudaGetSymbolAddress((void**)&kvlat, g_kvlat);
    cudaGetSymbolAddress((void**)&qc,    g_qc);
    cudaGetSymbolAddress((void**)&qr,    g_qr);
    cudaGetSymbolAddress((void**)&kc,    g_kc);
    cudaGetSymbolAddress((void**)&vv,    g_vv);
    cudaGetSymbolAddress((void**)&kr,    g_kr);
    cudaGetSymbolAddress((void**)&Qb,    g_Q);
    cudaGetSymbolAddress((void**)&Kb,    g_K);
    cudaGetSymbolAddress((void**)&Vb,    g_V);
    cudaGetSymbolAddress((void**)&al,    g_alpha);
    cudaGetSymbolAddress((void**)&xh,    g_xh);
    cudaGetSymbolAddress((void**)&xl,    g_xl);
    cudaGetSymbolAddress((void**)&qlh,   g_qlh);
    cudaGetSymbolAddress((void**)&qll,   g_qll);
    cudaGetSymbolAddress((void**)&kvh,   g_kvh);
    cudaGetSymbolAddress((void**)&kvl,   g_kvl);
    cudaGetSymbolAddress((void**)&mgh,   g_mgh);
    cudaGetSymbolAddress((void**)&mgl,   g_mgl);
    cudaGetSymbolAddress((void**)&wqdh,  g_wqd_h);
    cudaGetSymbolAddress((void**)&wqdl,  g_wqd_l);
    cudaGetSymbolAddress((void**)&wquh,  g_wqu_h);
    cudaGetSymbolAddress((void**)&wqul,  g_wqu_l);
    cudaGetSymbolAddress((void**)&wqrh,  g_wqr_h);
    cudaGetSymbolAddress((void**)&wqrl,  g_wqr_l);
    cudaGetSymbolAddress((void**)&wkdh,  g_wkd_h);
    cudaGetSymbolAddress((void**)&wkdl,  g_wkd_l);
    cudaGetSymbolAddress((void**)&wkuh,  g_wku_h);
    cudaGetSymbolAddress((void**)&wkul,  g_wku_l);
    cudaGetSymbolAddress((void**)&wvuh,  g_wvu_h);
    cudaGetSymbolAddress((void**)&wvul,  g_wvu_l);
    cudaGetSymbolAddress((void**)&wkrh,  g_wkr_h);
    cudaGetSymbolAddress((void**)&wkrl,  g_wkr_l);
    cudaGetSymbolAddress((void**)&woh,   g_wo_h);
    cudaGetSymbolAddress((void**)&wol,   g_wo_l);

    auto split = [&](const float* s, bf16* h, bf16* l, size_t n) {
        split_kernel<<<(int)(n / 1024), 256>>>(s, h, l, (int)n);
    };

    // splits: input + weights
    split(x,        xh,   xl,   (size_t)BT*DD);
    split(Wq_down,  wqdh, wqdl, (size_t)DD*CQQ);
    split(Wq_up,    wquh, wqul, (size_t)CQQ*2048);
    split(Wq_rope,  wqrh, wqrl, (size_t)CQQ*1024);
    split(Wkv_down, wkdh, wkdl, (size_t)DD*CKVV);
    split(Wk_up,    wkuh, wkul, (size_t)CKVV*2048);
    split(Wv_up,    wvuh, wvul, (size_t)CKVV*2048);
    split(Wk_rope,  wkrh, wkrl, (size_t)DD*1024);
    split(Wout,     woh,  wol,  (size_t)2048*DD);

    // latent projections + norms (norm emits split bf16)
    gemm_split<<<dim3(CQQ/128,  BT/128), 256>>>(xh, xl, wqdh, wqdl, qlat,  BT, CQQ,  DD);
    rmsnorm_split_kernel<<<BT, 256>>>(qlat, q_norm_w, qlh, qll, CQQ);
    gemm_split<<<dim3(CKVV/128, BT/128), 256>>>(xh, xl, wkdh, wkdl, kvlat, BT, CKVV, DD);
    rmsnorm_split_kernel<<<BT, 256>>>(kvlat, kv_norm_w, kvh, kvl, CKVV);

    // up projections
    gemm_split<<<dim3(2048/128, BT/128), 256>>>(qlh, qll, wquh, wqul, qc, BT, 2048, CQQ);
    gemm_split<<<dim3(1024/128, BT/128), 256>>>(qlh, qll, wqrh, wqrl, qr, BT, 1024, CQQ);
    gemm_split<<<dim3(2048/128, BT/128), 256>>>(kvh, kvl, wkuh, wkul, kc, BT, 2048, CKVV);
    gemm_split<<<dim3(2048/128, BT/128), 256>>>(kvh, kvl, wvuh, wvul, vv, BT, 2048, CKVV);
    gemm_split<<<dim3(1024/128, BT/128), 256>>>(xh, xl, wkrh, wkrl, kr, BT, 1024, DD);

    // gate
    float* out_alpha = (out_size >= BB*TT*DD + BB*TT) ? (out + (size_t)BB*TT*DD)
                                                      : nullptr;
    alpha_kernel<<<BT, 256>>>(x, Wgate, bgate, al, out_alpha);

    // build Q/K/V
    assemble_kernel<<<BT*NHH, 128>>>(qc, qr, kc, kr, vv, unc, Qb, Kb, Vb);

    // fused dual attention -> merged (split bf16)
    attn_kernel<<<BB*NHH*(TT/8), 256>>>(Qb, Kb, Vb, al, mgh, mgl);

    // output projection
    gemm_split<<<dim3(DD/128, BT/128), 256>>>(mgh, mgl, woh, wol, out, BT, DD, 2048);
}

// round 3
// speedup vs baseline: 4.7479x; 3.9318x over previous
#include <cuda_runtime.h>
#include <cuda_bf16.h>
#include <math.h>
#include <stdint.h>

// ---------------- problem constants ----------------
#define BB   2
#define TT   2048
#define DD   2048
#define NHH  16
#define HDD  128
#define RR   64
#define CQQ  1536
#define CKVV 512
#define BT   (BB*TT)       // 4096
#define DQK  192           // HD + R
#define DVV  128
#define HALFW 256          // WINDOW/2
#define RSCALE 0.07216878364870323f  // 1/sqrt(192)

typedef __nv_bfloat16 bf16;

// ---------------- scratch (device globals; no runtime alloc) ----------------
__device__ float g_qlat [(size_t)BT*CQQ];
__device__ float g_kvlat[(size_t)BT*CKVV];
__device__ float g_qc   [(size_t)BT*NHH*HDD];
__device__ float g_qr   [(size_t)BT*NHH*RR];
__device__ float g_kc   [(size_t)BT*NHH*HDD];
__device__ float g_vv   [(size_t)BT*NHH*HDD];
__device__ float g_kr   [(size_t)BT*NHH*RR];
__device__ float g_alpha[BT];

// attention operands, pre-split bf16, head-major: [bh][t][d]
__device__ bf16 g_Qh[(size_t)BB*NHH*TT*DQK], g_Ql[(size_t)BB*NHH*TT*DQK];
__device__ bf16 g_Kh[(size_t)BB*NHH*TT*DQK], g_Kl[(size_t)BB*NHH*TT*DQK];
__device__ bf16 g_Vh[(size_t)BB*NHH*TT*DVV], g_Vl[(size_t)BB*NHH*TT*DVV];

// bf16 split buffers (hi/lo) for GEMMs
__device__ bf16 g_xh [(size_t)BT*DD],    g_xl [(size_t)BT*DD];
__device__ bf16 g_qlh[(size_t)BT*CQQ],   g_qll[(size_t)BT*CQQ];
__device__ bf16 g_kvh[(size_t)BT*CKVV],  g_kvl[(size_t)BT*CKVV];
__device__ bf16 g_mgh[(size_t)BT*NHH*HDD], g_mgl[(size_t)BT*NHH*HDD];
__device__ bf16 g_wqd_h[(size_t)DD*CQQ],     g_wqd_l[(size_t)DD*CQQ];
__device__ bf16 g_wqu_h[(size_t)CQQ*2048],   g_wqu_l[(size_t)CQQ*2048];
__device__ bf16 g_wqr_h[(size_t)CQQ*1024],   g_wqr_l[(size_t)CQQ*1024];
__device__ bf16 g_wkd_h[(size_t)DD*CKVV],    g_wkd_l[(size_t)DD*CKVV];
__device__ bf16 g_wku_h[(size_t)CKVV*2048],  g_wku_l[(size_t)CKVV*2048];
__device__ bf16 g_wvu_h[(size_t)CKVV*2048],  g_wvu_l[(size_t)CKVV*2048];
__device__ bf16 g_wkr_h[(size_t)DD*1024],    g_wkr_l[(size_t)DD*1024];
__device__ bf16 g_wo_h [(size_t)2048*DD],    g_wo_l [(size_t)2048*DD];

// ---------------- ptx helpers ----------------
__device__ __forceinline__ void ldsm_x4(uint32_t* r, const void* p) {
    uint32_t a = (uint32_t)__cvta_generic_to_shared(p);
    asm volatile("ldmatrix.sync.aligned.m8n8.x4.shared.b16 {%0,%1,%2,%3}, [%4];"
                 : "=r"(r[0]), "=r"(r[1]), "=r"(r[2]), "=r"(r[3]) : "r"(a));
}
__device__ __forceinline__ void ldsm_x4t(uint32_t* r, const void* p) {
    uint32_t a = (uint32_t)__cvta_generic_to_shared(p);
    asm volatile("ldmatrix.sync.aligned.m8n8.x4.trans.shared.b16 {%0,%1,%2,%3}, [%4];"
                 : "=r"(r[0]), "=r"(r[1]), "=r"(r[2]), "=r"(r[3]) : "r"(a));
}
__device__ __forceinline__ void ldsm_x2t(uint32_t &r0, uint32_t &r1,
                                         const void* p) {
    uint32_t a = (uint32_t)__cvta_generic_to_shared(p);
    asm volatile("ldmatrix.sync.aligned.m8n8.x2.trans.shared.b16 {%0,%1}, [%2];"
                 : "=r"(r0), "=r"(r1) : "r"(a));
}
__device__ __forceinline__ void mma_bf16(float* c, const uint32_t* a,
                                         const uint32_t* b) {
    asm volatile(
        "mma.sync.aligned.m16n8k16.row.col.f32.bf16.bf16.f32 "
        "{%0,%1,%2,%3}, {%4,%5,%6,%7}, {%8,%9}, {%0,%1,%2,%3};"
        : "+f"(c[0]), "+f"(c[1]), "+f"(c[2]), "+f"(c[3])
        : "r"(a[0]), "r"(a[1]), "r"(a[2]), "r"(a[3]), "r"(b[0]), "r"(b[1]));
}
__device__ __forceinline__ void cpa16(void* s, const void* g) {
    uint32_t sa = (uint32_t)__cvta_generic_to_shared(s);
    asm volatile("cp.async.cg.shared.global [%0], [%1], 16;" :: "r"(sa), "l"(g));
}
#define CP_COMMIT asm volatile("cp.async.commit_group;")
#define CP_WAIT1  asm volatile("cp.async.wait_group 1;")
#define CP_WAIT0  asm volatile("cp.async.wait_group 0;")

__device__ __forceinline__ uint32_t pk(bf16 a, bf16 b) {
    __nv_bfloat162 t(a, b);
    return *reinterpret_cast<uint32_t*>(&t);
}

// ---------------- split fp32 -> (hi, lo) bf16 ----------------
__global__ __launch_bounds__(256) void split_kernel(
    const float* __restrict__ s, bf16* __restrict__ h,
    bf16* __restrict__ l, int n)
{
    int i = (blockIdx.x * 256 + threadIdx.x) * 4;
    if (i >= n) return;
    float4 v = *(const float4*)(s + i);
    bf16 h0 = __float2bfloat16(v.x), h1 = __float2bfloat16(v.y);
    bf16 h2 = __float2bfloat16(v.z), h3 = __float2bfloat16(v.w);
    bf16 l0 = __float2bfloat16(v.x - __bfloat162float(h0));
    bf16 l1 = __float2bfloat16(v.y - __bfloat162float(h1));
    bf16 l2 = __float2bfloat16(v.z - __bfloat162float(h2));
    bf16 l3 = __float2bfloat16(v.w - __bfloat162float(h3));
    *(__nv_bfloat162*)(h + i)     = __nv_bfloat162(h0, h1);
    *(__nv_bfloat162*)(h + i + 2) = __nv_bfloat162(h2, h3);
    *(__nv_bfloat162*)(l + i)     = __nv_bfloat162(l0, l1);
    *(__nv_bfloat162*)(l + i + 2) = __nv_bfloat162(l2, l3);
}

// ---------------- split-bf16 tensor-core GEMM with register prefetch -------
__global__ __launch_bounds__(256) void gemm_split(
    const bf16* __restrict__ Ah, const bf16* __restrict__ Al,
    const bf16* __restrict__ Bh, const bf16* __restrict__ Bl,
    float* __restrict__ C, int M, int N, int K)
{
    __shared__ __align__(16) bf16 sAh[128*40];
    __shared__ __align__(16) bf16 sAl[128*40];
    __shared__ __align__(16) bf16 sBh[32*136];
    __shared__ __align__(16) bf16 sBl[32*136];

    int tid = threadIdx.x;
    int bm = blockIdx.y, bn = blockIdx.x;
    int warp = tid >> 5, lane = tid & 31;
    int wm = warp >> 2, wn = warp & 3;

    float acc[4][4][4];
#pragma unroll
    for (int a = 0; a < 4; a++)
#pragma unroll
        for (int b = 0; b < 4; b++)
#pragma unroll
            for (int c = 0; c < 4; c++) acc[a][b][c] = 0.f;

    uint4 rah[2], ral[2], rbh[2], rbl[2];
    // prefetch k0 = 0
#pragma unroll
    for (int i = 0; i < 2; i++) {
        int v = tid + i * 256;
        int row = v >> 2, c = (v & 3) * 8;
        size_t g = (size_t)(bm * 128 + row) * K + c;
        rah[i] = *(const uint4*)(Ah + g);
        ral[i] = *(const uint4*)(Al + g);
    }
#pragma unroll
    for (int i = 0; i < 2; i++) {
        int v = tid + i * 256;
        int row = v >> 4, c = (v & 15) * 8;
        size_t g = (size_t)row * N + bn * 128 + c;
        rbh[i] = *(const uint4*)(Bh + g);
        rbl[i] = *(const uint4*)(Bl + g);
    }

    for (int k0 = 0; k0 < K; k0 += 32) {
        // store regs -> smem
#pragma unroll
        for (int i = 0; i < 2; i++) {
            int v = tid + i * 256;
            int row = v >> 2, c = (v & 3) * 8;
            *(uint4*)&sAh[row * 40 + c] = rah[i];
            *(uint4*)&sAl[row * 40 + c] = ral[i];
        }
#pragma unroll
        for (int i = 0; i < 2; i++) {
            int v = tid + i * 256;
            int row = v >> 4, c = (v & 15) * 8;
            *(uint4*)&sBh[row * 136 + c] = rbh[i];
            *(uint4*)&sBl[row * 136 + c] = rbl[i];
        }
        __syncthreads();

        if (k0 + 32 < K) {
#pragma unroll
            for (int i = 0; i < 2; i++) {
                int v = tid + i * 256;
                int row = v >> 2, c = (v & 3) * 8;
                size_t g = (size_t)(bm * 128 + row) * K + k0 + 32 + c;
                rah[i] = *(const uint4*)(Ah + g);
                ral[i] = *(const uint4*)(Al + g);
            }
#pragma unroll
            for (int i = 0; i < 2; i++) {
                int v = tid + i * 256;
                int row = v >> 4, c = (v & 15) * 8;
                size_t g = (size_t)(k0 + 32 + row) * N + bn * 128 + c;
                rbh[i] = *(const uint4*)(Bh + g);
                rbl[i] = *(const uint4*)(Bl + g);
            }
        }

#pragma unroll
        for (int kh = 0; kh < 2; kh++) {
            uint32_t bhf[4][2], blf[4][2];
#pragma unroll
            for (int nt = 0; nt < 4; nt++) {
                int brow = kh * 16 + (lane & 15);
                int bcol = wn * 32 + nt * 8;
                ldsm_x2t(bhf[nt][0], bhf[nt][1], &sBh[brow * 136 + bcol]);
                ldsm_x2t(blf[nt][0], blf[nt][1], &sBl[brow * 136 + bcol]);
            }
#pragma unroll
            for (int mt = 0; mt < 4; mt++) {
                int arow = wm * 64 + mt * 16 + (lane & 15);
                int acol = kh * 16 + (lane >> 4) * 8;
                uint32_t ah[4], al[4];
                ldsm_x4(ah, &sAh[arow * 40 + acol]);
                ldsm_x4(al, &sAl[arow * 40 + acol]);
#pragma unroll
                for (int nt = 0; nt < 4; nt++) {
                    mma_bf16(acc[mt][nt], ah, bhf[nt]);
                    mma_bf16(acc[mt][nt], ah, blf[nt]);
                    mma_bf16(acc[mt][nt], al, bhf[nt]);
                }
            }
        }
        __syncthreads();
    }

#pragma unroll
    for (int mt = 0; mt < 4; mt++) {
#pragma unroll
        for (int nt = 0; nt < 4; nt++) {
            int r0 = bm * 128 + wm * 64 + mt * 16 + (lane >> 2);
            int c0 = bn * 128 + wn * 32 + nt * 8 + (lane & 3) * 2;
            *(float2*)&C[(size_t)r0 * N + c0] =
                make_float2(acc[mt][nt][0], acc[mt][nt][1]);
            *(float2*)&C[(size_t)(r0 + 8) * N + c0] =
                make_float2(acc[mt][nt][2], acc[mt][nt][3]);
        }
    }
}

// ---------------- RMSNorm -> split bf16 outputs ----------------
__global__ __launch_bounds__(256) void rmsnorm_split_kernel(
    const float* __restrict__ x, const float* __restrict__ w,
    bf16* __restrict__ hi, bf16* __restrict__ lo, int n)
{
    const float* row = x + (size_t)blockIdx.x * n;
    float ss = 0.f;
    for (int i = threadIdx.x; i < n; i += 256) { float v = row[i]; ss += v*v; }
    __shared__ float sh[8];
    __shared__ float tot;
    int lane = threadIdx.x & 31, wp = threadIdx.x >> 5;
#pragma unroll
    for (int o = 16; o; o >>= 1) ss += __shfl_xor_sync(0xffffffffu, ss, o);
    if (lane == 0) sh[wp] = ss;
    __syncthreads();
    if (threadIdx.x == 0) {
        float s = 0.f;
        for (int i = 0; i < 8; i++) s += sh[i];
        tot = rsqrtf(s / n + 1e-6f);
    }
    __syncthreads();
    float rs = tot;
    bf16* hrow = hi + (size_t)blockIdx.x * n;
    bf16* lrow = lo + (size_t)blockIdx.x * n;
    for (int i = threadIdx.x; i < n; i += 256) {
        float y = row[i] * rs * w[i];
        bf16 h = __float2bfloat16(y);
        hrow[i] = h;
        lrow[i] = __float2bfloat16(y - __bfloat162float(h));
    }
}

// ---------------- gate alpha ----------------
__global__ __launch_bounds__(256) void alpha_kernel(
    const float* __restrict__ x, const float* __restrict__ wg,
    const float* __restrict__ bg, float* __restrict__ alpha,
    float* __restrict__ out_alpha)
{
    const float* row = x + (size_t)blockIdx.x * DD;
    float s = 0.f;
    for (int i = threadIdx.x; i < DD; i += 256) s += row[i] * wg[i];
    __shared__ float sh[8];
    int lane = threadIdx.x & 31, wp = threadIdx.x >> 5;
#pragma unroll
    for (int o = 16; o; o >>= 1) s += __shfl_xor_sync(0xffffffffu, s, o);
    if (lane == 0) sh[wp] = s;
    __syncthreads();
    if (threadIdx.x == 0) {
        float t = 0.f;
        for (int i = 0; i < 8; i++) t += sh[i];
        float z = t + bg[0];
        float a = 1.f / (1.f + expf(-z));
        alpha[blockIdx.x] = a;
        if (out_alpha) out_alpha[blockIdx.x] = a;
    }
}

// ---------------- assemble Q/K/V with EPE-RoPE (emit split bf16) -----------
__global__ __launch_bounds__(128) void assemble_kernel(
    const float* __restrict__ qc, const float* __restrict__ qr,
    const float* __restrict__ kc, const float* __restrict__ kr,
    const float* __restrict__ vv, const float* __restrict__ unc,
    bf16* __restrict__ Qh, bf16* __restrict__ Ql,
    bf16* __restrict__ Kh, bf16* __restrict__ Kl,
    bf16* __restrict__ Vh, bf16* __restrict__ Vl)
{
    int idx = blockIdx.x;
    int h  = idx % NHH;
    int bt = idx / NHH;
    int t  = bt % TT;
    int b  = bt / TT;
    __shared__ float cs[32], sn[32];
    int d = threadIdx.x;
    if (d < 32) {
        float u = unc[bt];
        u = fminf(fmaxf(u, 0.f), 1.f);
        float scale = 0.5f + 1.5f * u;
        float fi = (float)d / 32.0f;
        float theta = expf(-fi * logf(500000.0f));
        float fr = (float)t * theta * scale;
        cs[d] = cosf(fr);
        sn[d] = sinf(fr);
    }
    __syncthreads();
    size_t qkrow = ((size_t)(b*NHH + h))*TT + t;

    float qv0 = qc[(size_t)bt*2048 + h*128 + d];
    float kv0 = kc[(size_t)bt*2048 + h*128 + d];
    float vv0 = vv[(size_t)bt*2048 + h*128 + d];
    bf16 hh;
    hh = __float2bfloat16(qv0);
    Qh[qkrow*DQK + d] = hh; Ql[qkrow*DQK + d] = __float2bfloat16(qv0 - __bfloat162float(hh));
    hh = __float2bfloat16(kv0);
    Kh[qkrow*DQK + d] = hh; Kl[qkrow*DQK + d] = __float2bfloat16(kv0 - __bfloat162float(hh));
    hh = __float2bfloat16(vv0);
    Vh[qkrow*DVV + d] = hh; Vl[qkrow*DVV + d] = __float2bfloat16(vv0 - __bfloat162float(hh));

    if (d < 64) {
        const float* qrp = qr + (size_t)bt*1024 + h*64;
        const float* krp = kr + (size_t)bt*1024 + h*64;
        float qv, kv;
        if (d < 32) {
            float c = cs[d], s = sn[d];
            qv = qrp[d]*c - qrp[d+32]*s;
            kv = krp[d]*c - krp[d+32]*s;
        } else {
            int j = d - 32;
            float c = cs[j], s = sn[j];
            qv = qrp[j+32]*c + qrp[j]*s;
            kv = krp[j+32]*c + krp[j]*s;
        }
        hh = __float2bfloat16(qv);
        Qh[qkrow*DQK + 128 + d] = hh;
        Ql[qkrow*DQK + 128 + d] = __float2bfloat16(qv - __bfloat162float(hh));
        hh = __float2bfloat16(kv);
        Kh[qkrow*DQK + 128 + d] = hh;
        Kl[qkrow*DQK + 128 + d] = __float2bfloat16(kv - __bfloat162float(hh));
    }
}

// ---------------- tensor-core fused dual attention ----------------
// grid (T/64, B*NH), block 128 (4 warps). Warp w: query rows 16w..16w+15.
#define KSTR 200
#define VSTR 136
#define ATTN_SMEM ((64*KSTR*2 + 2*64*KSTR*2 + 2*64*VSTR*2) * 2)  // bytes

__global__ void __launch_bounds__(128, 1) attn_tc_kernel(
    const bf16* __restrict__ Qh, const bf16* __restrict__ Ql,
    const bf16* __restrict__ Kh, const bf16* __restrict__ Kl,
    const bf16* __restrict__ Vh, const bf16* __restrict__ Vl,
    const float* __restrict__ alpha,
    bf16* __restrict__ mgh, bf16* __restrict__ mgl)
{
    extern __shared__ __align__(16) bf16 smem[];
    bf16* sQh = smem;                  // 64*KSTR
    bf16* sQl = sQh + 64*KSTR;
    bf16* sKh = sQl + 64*KSTR;         // 2 bufs
    bf16* sKl = sKh + 2*64*KSTR;       // 2 bufs
    bf16* sVh = sKl + 2*64*KSTR;       // 2 bufs
    bf16* sVl = sVh + 2*64*VSTR;       // 2 bufs

    int tid = threadIdx.x, lane = tid & 31, warp = tid >> 5;
    int qt = blockIdx.x * 64;
    int bh = blockIdx.y;
    int b = bh >> 4, h = bh & 15;
    size_t base = (size_t)bh * TT;

    // Q tile load (group 0 together with k/v tile 0)
    for (int i = tid; i < 64*24; i += 128) {
        int r = i / 24, c = (i % 24) * 8;
        size_t g = (base + qt + r) * DQK + c;
        cpa16(&sQh[r*KSTR + c], Qh + g);
        cpa16(&sQl[r*KSTR + c], Ql + g);
    }
    // tile 0 K/V
    for (int i = tid; i < 64*24; i += 128) {
        int r = i / 24, c = (i % 24) * 8;
        size_t g = (base + r) * DQK + c;
        cpa16(&sKh[r*KSTR + c], Kh + g);
        cpa16(&sKl[r*KSTR + c], Kl + g);
    }
    for (int i = tid; i < 64*16; i += 128) {
        int r = i / 16, c = (i % 16) * 8;
        size_t g = (base + r) * DVV + c;
        cpa16(&sVh[r*VSTR + c], Vh + g);
        cpa16(&sVl[r*VSTR + c], Vl + g);
    }
    CP_COMMIT;

    int q0 = qt + 16*warp + (lane >> 2);
    int q1 = q0 + 8;
    int winlo = ((qt >> 8) << 8) - HALFW;
    if (winlo < 0) winlo = 0;

    float ob[16][4], ow[16][4];
#pragma unroll
    for (int n = 0; n < 16; n++)
#pragma unroll
        for (int j = 0; j < 4; j++) { ob[n][j] = 0.f; ow[n][j] = 0.f; }
    float m0 = -1e30f, m1 = -1e30f;
    float lb0 = 0.f, lb1 = 0.f, lw0 = 0.f, lw1 = 0.f;

    for (int t = 0; t < 32; t++) {
        int kt = t * 64;
        int nb = (t + 1) & 1;
        if (t + 1 < 32) {
            int kn = kt + 64;
            for (int i = tid; i < 64*24; i += 128) {
                int r = i / 24, c = (i % 24) * 8;
                size_t g = (base + kn + r) * DQK + c;
                cpa16(&sKh[nb*64*KSTR + r*KSTR + c], Kh + g);
                cpa16(&sKl[nb*64*KSTR + r*KSTR + c], Kl + g);
            }
            for (int i = tid; i < 64*16; i += 128) {
                int r = i / 16, c = (i % 16) * 8;
                size_t g = (base + kn + r) * DVV + c;
                cpa16(&sVh[nb*64*VSTR + r*VSTR + c], Vh + g);
                cpa16(&sVl[nb*64*VSTR + r*VSTR + c], Vl + g);
            }
        }
        CP_COMMIT;
        CP_WAIT1;
        __syncthreads();

        const bf16* bKh = sKh + (t & 1) * 64 * KSTR;
        const bf16* bVh = sVh + (t & 1) * 64 * VSTR;

        // ---- S = Q K^T (3 split chains) ----
        float sacc[8][4];
#pragma unroll
        for (int n = 0; n < 8; n++)
#pragma unroll
            for (int j = 0; j < 4; j++) sacc[n][j] = 0.f;

#pragma unroll
        for (int ks = 0; ks < 12; ks++) {
            uint32_t qhf[4], qlf[4];
            const bf16* ap = &sQh[(16*warp + (lane & 15))*KSTR + ks*16 + (lane >> 4)*8];
            ldsm_x4(qhf, ap);
            ldsm_x4(qlf, ap + 64*KSTR);
#pragma unroll
            for (int np = 0; np < 4; np++) {
                int g2 = lane >> 3;
                int krow = np*16 + (g2 >> 1)*8 + (lane & 7);
                int kcol = ks*16 + (g2 & 1)*8;
                const bf16* bp = &bKh[krow*KSTR + kcol];
                uint32_t khf[4], klf[4];
                ldsm_x4(khf, bp);
                ldsm_x4(klf, bp + 2*64*KSTR);
                mma_bf16(sacc[2*np],   qhf, khf);
                mma_bf16(sacc[2*np],   qhf, klf);
                mma_bf16(sacc[2*np],   qlf, khf);
                mma_bf16(sacc[2*np+1], qhf, khf + 2);
                mma_bf16(sacc[2*np+1], qhf, klf + 2);
                mma_bf16(sacc[2*np+1], qlf, khf + 2);
            }
        }

        // ---- online softmax ----
        float tm0 = -1e30f, tm1 = -1e30f;
#pragma unroll
        for (int n = 0; n < 8; n++) {
            tm0 = fmaxf(tm0, fmaxf(sacc[n][0], sacc[n][1]));
            tm1 = fmaxf(tm1, fmaxf(sacc[n][2], sacc[n][3]));
        }
        tm0 *= RSCALE; tm1 *= RSCALE;
        tm0 = fmaxf(tm0, __shfl_xor_sync(0xffffffffu, tm0, 1));
        tm0 = fmaxf(tm0, __shfl_xor_sync(0xffffffffu, tm0, 2));
        tm1 = fmaxf(tm1, __shfl_xor_sync(0xffffffffu, tm1, 1));
        tm1 = fmaxf(tm1, __shfl_xor_sync(0xffffffffu, tm1, 2));
        float mn0 = fmaxf(m0, tm0), mn1 = fmaxf(m1, tm1);
        float c0 = __expf(m0 - mn0), c1 = __expf(m1 - mn1);
        m0 = mn0; m1 = mn1;
        lb0 *= c0; lb1 *= c1; lw0 *= c0; lw1 *= c1;
        if (c0 < 1.f || c1 < 1.f) {
#pragma unroll
            for (int n = 0; n < 16; n++) {
                ob[n][0] *= c0; ob[n][1] *= c0; ob[n][2] *= c1; ob[n][3] *= c1;
                ow[n][0] *= c0; ow[n][1] *= c0; ow[n][2] *= c1; ow[n][3] *= c1;
            }
        }

        bool artile = (kt >= winlo) && (kt <= qt);
        float sb0 = 0.f, sb1 = 0.f, sw0 = 0.f, sw1 = 0.f;
#pragma unroll
        for (int n = 0; n < 8; n++) {
            float p0 = __expf(sacc[n][0]*RSCALE - mn0);
            float p1 = __expf(sacc[n][1]*RSCALE - mn0);
            float p2 = __expf(sacc[n][2]*RSCALE - mn1);
            float p3 = __expf(sacc[n][3]*RSCALE - mn1);
            sacc[n][0] = p0; sacc[n][1] = p1; sacc[n][2] = p2; sacc[n][3] = p3;
            sb0 += p0 + p1; sb1 += p2 + p3;
            if (artile) {
                int keyc = kt + 8*n + 2*(lane & 3);
                sw0 += ((keyc   <= q0) ? p0 : 0.f) + ((keyc+1 <= q0) ? p1 : 0.f);
                sw1 += ((keyc   <= q1) ? p2 : 0.f) + ((keyc+1 <= q1) ? p3 : 0.f);
            }
        }
        sb0 += __shfl_xor_sync(0xffffffffu, sb0, 1); sb0 += __shfl_xor_sync(0xffffffffu, sb0, 2);
        sb1 += __shfl_xor_sync(0xffffffffu, sb1, 1); sb1 += __shfl_xor_sync(0xffffffffu, sb1, 2);
        sw0 += __shfl_xor_sync(0xffffffffu, sw0, 1); sw0 += __shfl_xor_sync(0xffffffffu, sw0, 2);
        sw1 += __shfl_xor_sync(0xffffffffu, sw1, 1); sw1 += __shfl_xor_sync(0xffffffffu, sw1, 2);
        lb0 += sb0; lb1 += sb1; lw0 += sw0; lw1 += sw1;

        // ---- P V (bidir + windowed AR) ----
#pragma unroll
        for (int j = 0; j < 4; j++) {
            float v0 = sacc[2*j][0],   v1 = sacc[2*j][1];
            float v2 = sacc[2*j][2],   v3 = sacc[2*j][3];
            float v4 = sacc[2*j+1][0], v5 = sacc[2*j+1][1];
            float v6 = sacc[2*j+1][2], v7 = sacc[2*j+1][3];
            bf16 h0 = __float2bfloat16(v0), h1 = __float2bfloat16(v1);
            bf16 h2 = __float2bfloat16(v2), h3 = __float2bfloat16(v3);
            bf16 h4 = __float2bfloat16(v4), h5 = __float2bfloat16(v5);
            bf16 h6 = __float2bfloat16(v6), h7 = __float2bfloat16(v7);
            bf16 e0 = __float2bfloat16(v0 - __bfloat162float(h0));
            bf16 e1 = __float2bfloat16(v1 - __bfloat162float(h1));
            bf16 e2 = __float2bfloat16(v2 - __bfloat162float(h2));
            bf16 e3 = __float2bfloat16(v3 - __bfloat162float(h3));
            bf16 e4 = __float2bfloat16(v4 - __bfloat162float(h4));
            bf16 e5 = __float2bfloat16(v5 - __bfloat162float(h5));
            bf16 e6 = __float2bfloat16(v6 - __bfloat162float(h6));
            bf16 e7 = __float2bfloat16(v7 - __bfloat162float(h7));
            uint32_t ph[4] = { pk(h0,h1), pk(h2,h3), pk(h4,h5), pk(h6,h7) };
            uint32_t pl[4] = { pk(e0,e1), pk(e2,e3), pk(e4,e5), pk(e6,e7) };
            uint32_t wh[4], wl[4];
            if (artile) {
                bf16 z = __float2bfloat16(0.f);
                int kc = kt + 16*j + 2*(lane & 3);
                bool a0 = kc   <= q0, a1 = kc+1 <= q0;
                bool b0m = kc  <= q1, b1m = kc+1 <= q1;
                bool a2 = kc+8 <= q0, a3 = kc+9 <= q0;
                bool b2m = kc+8 <= q1, b3m = kc+9 <= q1;
                wh[0] = pk(a0?h0:z, a1?h1:z);  wl[0] = pk(a0?e0:z, a1?e1:z);
                wh[1] = pk(b0m?h2:z, b1m?h3:z); wl[1] = pk(b0m?e2:z, b1m?e3:z);
                wh[2] = pk(a2?h4:z, a3?h5:z);  wl[2] = pk(a2?e4:z, a3?e5:z);
                wh[3] = pk(b2m?h6:z, b3m?h7:z); wl[3] = pk(b2m?e6:z, b3m?e7:z);
            }
#pragma unroll
            for (int np = 0; np < 8; np++) {
                int g2 = lane >> 3;
                int vrow = 16*j + (g2 & 1)*8 + (lane & 7);
                int vcol = np*16 + (g2 >> 1)*8;
                const bf16* vp = &bVh[vrow*VSTR + vcol];
                uint32_t vhf[4], vlf[4];
                ldsm_x4t(vhf, vp);
                ldsm_x4t(vlf, vp + 2*64*VSTR);
                mma_bf16(ob[2*np],   ph, vhf);
                mma_bf16(ob[2*np],   ph, vlf);
                mma_bf16(ob[2*np],   pl, vhf);
                mma_bf16(ob[2*np+1], ph, vhf + 2);
                mma_bf16(ob[2*np+1], ph, vlf + 2);
                mma_bf16(ob[2*np+1], pl, vhf + 2);
                if (artile) {
                    mma_bf16(ow[2*np],   wh, vhf);
                    mma_bf16(ow[2*np],   wh, vlf);
                    mma_bf16(ow[2*np],   wl, vhf);
                    mma_bf16(ow[2*np+1], wh, vhf + 2);
                    mma_bf16(ow[2*np+1], wh, vlf + 2);
                    mma_bf16(ow[2*np+1], wl, vhf + 2);
                }
            }
        }
        __syncthreads();
    }

    // ---- epilogue: gate-merge, split-bf16 store ----
    float a0 = alpha[(size_t)b*TT + q0];
    float a1 = alpha[(size_t)b*TT + q1];
    float ilb0 = 1.f/lb0, ilb1 = 1.f/lb1, ilw0 = 1.f/lw0, ilw1 = 1.f/lw1;
    size_t r0o = ((size_t)b*TT + q0)*2048 + (size_t)h*128;
    size_t r1o = ((size_t)b*TT + q1)*2048 + (size_t)h*128;
#pragma unroll
    for (int n = 0; n < 16; n++) {
        int d = 8*n + 2*(lane & 3);
        float o00 = a0*ob[n][0]*ilb0 + (1.f-a0)*ow[n][0]*ilw0;
        float o01 = a0*ob[n][1]*ilb0 + (1.f-a0)*ow[n][1]*ilw0;
        float o10 = a1*ob[n][2]*ilb1 + (1.f-a1)*ow[n][2]*ilw1;
        float o11 = a1*ob[n][3]*ilb1 + (1.f-a1)*ow[n][3]*ilw1;
        bf16 h00 = __float2bfloat16(o00), h01 = __float2bfloat16(o01);
        bf16 h10 = __float2bfloat16(o10), h11 = __float2bfloat16(o11);
        *(uint32_t*)(mgh + r0o + d) = pk(h00, h01);
        *(uint32_t*)(mgh + r1o + d) = pk(h10, h11);
        *(uint32_t*)(mgl + r0o + d) = pk(
            __float2bfloat16(o00 - __bfloat162float(h00)),
            __float2bfloat16(o01 - __bfloat162float(h01)));
        *(uint32_t*)(mgl + r1o + d) = pk(
            __float2bfloat16(o10 - __bfloat162float(h10)),
            __float2bfloat16(o11 - __bfloat162float(h11)));
    }
}

// ---------------- launcher ----------------
extern "C" void kernel_launch(void* const* d_in, const int* in_sizes, int n_in,
                              void* d_out, int out_size)
{
    (void)in_sizes; (void)n_in;
    const float* x        = (const float*)d_in[0];
    const float* unc      = (const float*)d_in[1];
    const float* Wq_down  = (const float*)d_in[2];
    const float* q_norm_w = (const float*)d_in[3];
    const float* Wq_up    = (const float*)d_in[4];
    const float* Wq_rope  = (const float*)d_in[5];
    const float* Wkv_down = (const float*)d_in[6];
    const float* kv_norm_w= (const float*)d_in[7];
    const float* Wk_up    = (const float*)d_in[8];
    const float* Wv_up    = (const float*)d_in[9];
    const float* Wk_rope  = (const float*)d_in[10];
    const float* Wout     = (const float*)d_in[11];
    const float* Wgate    = (const float*)d_in[12];
    const float* bgate    = (const float*)d_in[13];
    float* out = (float*)d_out;

    float *qlat, *kvlat, *qc, *qr, *kc, *vv, *kr, *al;
    bf16 *Qh,*Ql,*Kh,*Kl,*Vh,*Vl;
    bf16 *xh,*xl,*qlh,*qll,*kvh,*kvl,*mgh,*mgl;
    bf16 *wqdh,*wqdl,*wquh,*wqul,*wqrh,*wqrl,*wkdh,*wkdl;
    bf16 *wkuh,*wkul,*wvuh,*wvul,*wkrh,*wkrl,*woh,*wol;
    cudaGetSymbolAddress((void**)&qlat,  g_qlat);
    cudaGetSymbolAddress((void**)&kvlat, g_kvlat);
    cudaGetSymbolAddress((void**)&qc,    g_qc);
    cudaGetSymbolAddress((void**)&qr,    g_qr);
    cudaGetSymbolAddress((void**)&kc,    g_kc);
    cudaGetSymbolAddress((void**)&vv,    g_vv);
    cudaGetSymbolAddress((void**)&kr,    g_kr);
    cudaGetSymbolAddress((void**)&al,    g_alpha);
    cudaGetSymbolAddress((void**)&Qh,    g_Qh);
    cudaGetSymbolAddress((void**)&Ql,    g_Ql);
    cudaGetSymbolAddress((void**)&Kh,    g_Kh);
    cudaGetSymbolAddress((void**)&Kl,    g_Kl);
    cudaGetSymbolAddress((void**)&Vh,    g_Vh);
    cudaGetSymbolAddress((void**)&Vl,    g_Vl);
    cudaGetSymbolAddress((void**)&xh,    g_xh);
    cudaGetSymbolAddress((void**)&xl,    g_xl);
    cudaGetSymbolAddress((void**)&qlh,   g_qlh);
    cudaGetSymbolAddress((void**)&qll,   g_qll);
    cudaGetSymbolAddress((void**)&kvh,   g_kvh);
    cudaGetSymbolAddress((void**)&kvl,   g_kvl);
    cudaGetSymbolAddress((void**)&mgh,   g_mgh);
    cudaGetSymbolAddress((void**)&mgl,   g_mgl);
    cudaGetSymbolAddress((void**)&wqdh,  g_wqd_h);
    cudaGetSymbolAddress((void**)&wqdl,  g_wqd_l);
    cudaGetSymbolAddress((void**)&wquh,  g_wqu_h);
    cudaGetSymbolAddress((void**)&wqul,  g_wqu_l);
    cudaGetSymbolAddress((void**)&wqrh,  g_wqr_h);
    cudaGetSymbolAddress((void**)&wqrl,  g_wqr_l);
    cudaGetSymbolAddress((void**)&wkdh,  g_wkd_h);
    cudaGetSymbolAddress((void**)&wkdl,  g_wkd_l);
    cudaGetSymbolAddress((void**)&wkuh,  g_wku_h);
    cudaGetSymbolAddress((void**)&wkul,  g_wku_l);
    cudaGetSymbolAddress((void**)&wvuh,  g_wvu_h);
    cudaGetSymbolAddress((void**)&wvul,  g_wvu_l);
    cudaGetSymbolAddress((void**)&wkrh,  g_wkr_h);
    cudaGetSymbolAddress((void**)&wkrl,  g_wkr_l);
    cudaGetSymbolAddress((void**)&woh,   g_wo_h);
    cudaGetSymbolAddress((void**)&wol,   g_wo_l);

    cudaFuncSetAttribute(attn_tc_kernel,
                         cudaFuncAttributeMaxDynamicSharedMemorySize, ATTN_SMEM);

    auto split = [&](const float* s, bf16* h, bf16* l, size_t n) {
        split_kernel<<<(int)(n / 1024), 256>>>(s, h, l, (int)n);
    };

    split(x,        xh,   xl,   (size_t)BT*DD);
    split(Wq_down,  wqdh, wqdl, (size_t)DD*CQQ);
    split(Wq_up,    wquh, wqul, (size_t)CQQ*2048);
    split(Wq_rope,  wqrh, wqrl, (size_t)CQQ*1024);
    split(Wkv_down, wkdh, wkdl, (size_t)DD*CKVV);
    split(Wk_up,    wkuh, wkul, (size_t)CKVV*2048);
    split(Wv_up,    wvuh, wvul, (size_t)CKVV*2048);
    split(Wk_rope,  wkrh, wkrl, (size_t)DD*1024);
    split(Wout,     woh,  wol,  (size_t)2048*DD);

    gemm_split<<<dim3(CQQ/128,  BT/128), 256>>>(xh, xl, wqdh, wqdl, qlat,  BT, CQQ,  DD);
    rmsnorm_split_kernel<<<BT, 256>>>(qlat, q_norm_w, qlh, qll, CQQ);
    gemm_split<<<dim3(CKVV/128, BT/128), 256>>>(xh, xl, wkdh, wkdl, kvlat, BT, CKVV, DD);
    rmsnorm_split_kernel<<<BT, 256>>>(kvlat, kv_norm_w, kvh, kvl, CKVV);

    gemm_split<<<dim3(2048/128, BT/128), 256>>>(qlh, qll, wquh, wqul, qc, BT, 2048, CQQ);
    gemm_split<<<dim3(1024/128, BT/128), 256>>>(qlh, qll, wqrh, wqrl, qr, BT, 1024, CQQ);
    gemm_split<<<dim3(2048/128, BT/128), 256>>>(kvh, kvl, wkuh, wkul, kc, BT, 2048, CKVV);
    gemm_split<<<dim3(2048/128, BT/128), 256>>>(kvh, kvl, wvuh, wvul, vv, BT, 2048, CKVV);
    gemm_split<<<dim3(1024/128, BT/128), 256>>>(xh, xl, wkrh, wkrl, kr, BT, 1024, DD);

    float* out_alpha = (out_size >= BB*TT*DD + BB*TT) ? (out + (size_t)BB*TT*DD)
                                                      : nullptr;
    alpha_kernel<<<BT, 256>>>(x, Wgate, bgate, al, out_alpha);

    assemble_kernel<<<BT*NHH, 128>>>(qc, qr, kc, kr, vv, unc,
                                     Qh, Ql, Kh, Kl, Vh, Vl);

    attn_tc_kernel<<<dim3(TT/64, BB*NHH), 128, ATTN_SMEM>>>(
        Qh, Ql, Kh, Kl, Vh, Vl, al, mgh, mgl);

    gemm_split<<<dim3(DD/128, BT/128), 256>>>(mgh, mgl, woh, wol, out, BT, DD, 2048);
}

// round 4
// speedup vs baseline: 4.8094x; 1.0129x over previous
#include <cuda_runtime.h>
#include <cuda_bf16.h>
#include <math.h>
#include <stdint.h>

// ---------------- problem constants ----------------
#define BB   2
#define TT   2048
#define DD   2048
#define NHH  16
#define HDD  128
#define RR   64
#define CQQ  1536
#define CKVV 512
#define BT   (BB*TT)       // 4096
#define DQK  192           // HD + R
#define DVV  128
#define HALFW 256          // WINDOW/2
#define RSCALE 0.07216878364870323f  // 1/sqrt(192)

typedef __nv_bfloat16 bf16;

// ---------------- scratch (device globals; no runtime alloc) ----------------
__device__ float g_qlat [(size_t)BT*CQQ];
__device__ float g_kvlat[(size_t)BT*CKVV];
__device__ float g_qc   [(size_t)BT*NHH*HDD];
__device__ float g_qr   [(size_t)BT*NHH*RR];
__device__ float g_kc   [(size_t)BT*NHH*HDD];
__device__ float g_vv   [(size_t)BT*NHH*HDD];
__device__ float g_kr   [(size_t)BT*NHH*RR];
__device__ float g_alpha[BT];

// attention operands, pre-split bf16, head-major: [bh][t][d]
__device__ bf16 g_Qh[(size_t)BB*NHH*TT*DQK], g_Ql[(size_t)BB*NHH*TT*DQK];
__device__ bf16 g_Kh[(size_t)BB*NHH*TT*DQK], g_Kl[(size_t)BB*NHH*TT*DQK];
__device__ bf16 g_Vh[(size_t)BB*NHH*TT*DVV], g_Vl[(size_t)BB*NHH*TT*DVV];

// bf16 split buffers (hi/lo) for GEMMs
__device__ bf16 g_xh [(size_t)BT*DD],    g_xl [(size_t)BT*DD];
__device__ bf16 g_qlh[(size_t)BT*CQQ],   g_qll[(size_t)BT*CQQ];
__device__ bf16 g_kvh[(size_t)BT*CKVV],  g_kvl[(size_t)BT*CKVV];
__device__ bf16 g_mgh[(size_t)BT*NHH*HDD], g_mgl[(size_t)BT*NHH*HDD];
__device__ bf16 g_wqd_h[(size_t)DD*CQQ],     g_wqd_l[(size_t)DD*CQQ];
__device__ bf16 g_wqu_h[(size_t)CQQ*2048],   g_wqu_l[(size_t)CQQ*2048];
__device__ bf16 g_wqr_h[(size_t)CQQ*1024],   g_wqr_l[(size_t)CQQ*1024];
__device__ bf16 g_wkd_h[(size_t)DD*CKVV],    g_wkd_l[(size_t)DD*CKVV];
__device__ bf16 g_wku_h[(size_t)CKVV*2048],  g_wku_l[(size_t)CKVV*2048];
__device__ bf16 g_wvu_h[(size_t)CKVV*2048],  g_wvu_l[(size_t)CKVV*2048];
__device__ bf16 g_wkr_h[(size_t)DD*1024],    g_wkr_l[(size_t)DD*1024];
__device__ bf16 g_wo_h [(size_t)2048*DD],    g_wo_l [(size_t)2048*DD];

// ---------------- ptx helpers ----------------
__device__ __forceinline__ void ldsm_x4(uint32_t* r, const void* p) {
    uint32_t a = (uint32_t)__cvta_generic_to_shared(p);
    asm volatile("ldmatrix.sync.aligned.m8n8.x4.shared.b16 {%0,%1,%2,%3}, [%4];"
                 : "=r"(r[0]), "=r"(r[1]), "=r"(r[2]), "=r"(r[3]) : "r"(a));
}
__device__ __forceinline__ void ldsm_x4t(uint32_t* r, const void* p) {
    uint32_t a = (uint32_t)__cvta_generic_to_shared(p);
    asm volatile("ldmatrix.sync.aligned.m8n8.x4.trans.shared.b16 {%0,%1,%2,%3}, [%4];"
                 : "=r"(r[0]), "=r"(r[1]), "=r"(r[2]), "=r"(r[3]) : "r"(a));
}
__device__ __forceinline__ void ldsm_x2t(uint32_t &r0, uint32_t &r1,
                                         const void* p) {
    uint32_t a = (uint32_t)__cvta_generic_to_shared(p);
    asm volatile("ldmatrix.sync.aligned.m8n8.x2.trans.shared.b16 {%0,%1}, [%2];"
                 : "=r"(r0), "=r"(r1) : "r"(a));
}
__device__ __forceinline__ void mma_bf16(float* c, const uint32_t* a,
                                         const uint32_t* b) {
    asm volatile(
        "mma.sync.aligned.m16n8k16.row.col.f32.bf16.bf16.f32 "
        "{%0,%1,%2,%3}, {%4,%5,%6,%7}, {%8,%9}, {%0,%1,%2,%3};"
        : "+f"(c[0]), "+f"(c[1]), "+f"(c[2]), "+f"(c[3])
        : "r"(a[0]), "r"(a[1]), "r"(a[2]), "r"(a[3]), "r"(b[0]), "r"(b[1]));
}
__device__ __forceinline__ void cpa16(void* s, const void* g) {
    uint32_t sa = (uint32_t)__cvta_generic_to_shared(s);
    asm volatile("cp.async.cg.shared.global [%0], [%1], 16;" :: "r"(sa), "l"(g));
}
#define CP_COMMIT asm volatile("cp.async.commit_group;")
#define CP_WAIT1  asm volatile("cp.async.wait_group 1;")
#define CP_WAIT0  asm volatile("cp.async.wait_group 0;")

__device__ __forceinline__ uint32_t pk(bf16 a, bf16 b) {
    __nv_bfloat162 t(a, b);
    return *reinterpret_cast<uint32_t*>(&t);
}

// ---------------- split fp32 -> (hi, lo) bf16 ----------------
__global__ __launch_bounds__(256) void split_kernel(
    const float* __restrict__ s, bf16* __restrict__ h,
    bf16* __restrict__ l, int n)
{
    int i = (blockIdx.x * 256 + threadIdx.x) * 4;
    if (i >= n) return;
    float4 v = *(const float4*)(s + i);
    bf16 h0 = __float2bfloat16(v.x), h1 = __float2bfloat16(v.y);
    bf16 h2 = __float2bfloat16(v.z), h3 = __float2bfloat16(v.w);
    bf16 l0 = __float2bfloat16(v.x - __bfloat162float(h0));
    bf16 l1 = __float2bfloat16(v.y - __bfloat162float(h1));
    bf16 l2 = __float2bfloat16(v.z - __bfloat162float(h2));
    bf16 l3 = __float2bfloat16(v.w - __bfloat162float(h3));
    *(__nv_bfloat162*)(h + i)     = __nv_bfloat162(h0, h1);
    *(__nv_bfloat162*)(h + i + 2) = __nv_bfloat162(h2, h3);
    *(__nv_bfloat162*)(l + i)     = __nv_bfloat162(l0, l1);
    *(__nv_bfloat162*)(l + i + 2) = __nv_bfloat162(l2, l3);
}

// ---------------- split-bf16 TC GEMM, 2-stage cp.async pipeline ------------
// C[M,N] = A[M,K] @ B[K,N]; M,N mult 128, K mult 32.
// dynamic smem: 2 stages x (sAh 128x40 | sAl 128x40 | sBh 32x136 | sBl 32x136)
#define GS_A   (128*40)
#define GS_B   (32*136)
#define GS_STG (2*GS_A + 2*GS_B)            // elems per stage = 18944
#define GS_SMEM (2*GS_STG*2)                // bytes = 75776

__global__ __launch_bounds__(256) void gemm_split(
    const bf16* __restrict__ Ah, const bf16* __restrict__ Al,
    const bf16* __restrict__ Bh, const bf16* __restrict__ Bl,
    float* __restrict__ C, int M, int N, int K)
{
    extern __shared__ __align__(16) bf16 gsm[];

    int tid = threadIdx.x;
    int bm = blockIdx.y, bn = blockIdx.x;
    int warp = tid >> 5, lane = tid & 31;
    int wm = warp >> 2, wn = warp & 3;

    // per-thread load coords
    int arow = tid >> 2, ac = (tid & 3) * 8;          // +row 64 for i=1
    int brow = tid >> 4, bc = (tid & 15) * 8;         // +row 16 for i=1

    float acc[4][4][4];
#pragma unroll
    for (int a = 0; a < 4; a++)
#pragma unroll
        for (int b = 0; b < 4; b++)
#pragma unroll
            for (int c = 0; c < 4; c++) acc[a][b][c] = 0.f;

    int nk = K >> 5;

    auto issue = [&](int stage, int k0) {
        bf16* sAh = gsm + stage * GS_STG;
        bf16* sAl = sAh + GS_A;
        bf16* sBh = sAl + GS_A;
        bf16* sBl = sBh + GS_B;
#pragma unroll
        for (int i = 0; i < 2; i++) {
            int r = arow + i * 64;
            size_t g = (size_t)(bm * 128 + r) * K + k0 + ac;
            cpa16(&sAh[r * 40 + ac], Ah + g);
            cpa16(&sAl[r * 40 + ac], Al + g);
        }
#pragma unroll
        for (int i = 0; i < 2; i++) {
            int r = brow + i * 16;
            size_t g = (size_t)(k0 + r) * N + bn * 128 + bc;
            cpa16(&sBh[r * 136 + bc], Bh + g);
            cpa16(&sBl[r * 136 + bc], Bl + g);
        }
    };

    issue(0, 0);
    CP_COMMIT;

    for (int it = 0; it < nk; it++) {
        if (it + 1 < nk) {
            issue((it + 1) & 1, (it + 1) << 5);
            CP_COMMIT;
            CP_WAIT1;
        } else {
            CP_WAIT0;
        }
        __syncthreads();

        bf16* sAh = gsm + (it & 1) * GS_STG;
        bf16* sAl = sAh + GS_A;
        bf16* sBh = sAl + GS_A;
        bf16* sBl = sBh + GS_B;

#pragma unroll
        for (int kh = 0; kh < 2; kh++) {
            uint32_t bhf[4][2], blf[4][2];
#pragma unroll
            for (int nt = 0; nt < 4; nt++) {
                int br = kh * 16 + (lane & 15);
                int bcl = wn * 32 + nt * 8;
                ldsm_x2t(bhf[nt][0], bhf[nt][1], &sBh[br * 136 + bcl]);
                ldsm_x2t(blf[nt][0], blf[nt][1], &sBl[br * 136 + bcl]);
            }
#pragma unroll
            for (int mt = 0; mt < 4; mt++) {
                int ar = wm * 64 + mt * 16 + (lane & 15);
                int acl = kh * 16 + (lane >> 4) * 8;
                uint32_t ah[4], al[4];
                ldsm_x4(ah, &sAh[ar * 40 + acl]);
                ldsm_x4(al, &sAl[ar * 40 + acl]);
#pragma unroll
                for (int nt = 0; nt < 4; nt++) {
                    mma_bf16(acc[mt][nt], ah, bhf[nt]);
                    mma_bf16(acc[mt][nt], ah, blf[nt]);
                    mma_bf16(acc[mt][nt], al, bhf[nt]);
                }
            }
        }
        __syncthreads();
    }

#pragma unroll
    for (int mt = 0; mt < 4; mt++) {
#pragma unroll
        for (int nt = 0; nt < 4; nt++) {
            int r0 = bm * 128 + wm * 64 + mt * 16 + (lane >> 2);
            int c0 = bn * 128 + wn * 32 + nt * 8 + (lane & 3) * 2;
            *(float2*)&C[(size_t)r0 * N + c0] =
                make_float2(acc[mt][nt][0], acc[mt][nt][1]);
            *(float2*)&C[(size_t)(r0 + 8) * N + c0] =
                make_float2(acc[mt][nt][2], acc[mt][nt][3]);
        }
    }
}

// ---------------- RMSNorm -> split bf16 outputs ----------------
__global__ __launch_bounds__(256) void rmsnorm_split_kernel(
    const float* __restrict__ x, const float* __restrict__ w,
    bf16* __restrict__ hi, bf16* __restrict__ lo, int n)
{
    const float* row = x + (size_t)blockIdx.x * n;
    float ss = 0.f;
    for (int i = threadIdx.x; i < n; i += 256) { float v = row[i]; ss += v*v; }
    __shared__ float sh[8];
    __shared__ float tot;
    int lane = threadIdx.x & 31, wp = threadIdx.x >> 5;
#pragma unroll
    for (int o = 16; o; o >>= 1) ss += __shfl_xor_sync(0xffffffffu, ss, o);
    if (lane == 0) sh[wp] = ss;
    __syncthreads();
    if (threadIdx.x == 0) {
        float s = 0.f;
        for (int i = 0; i < 8; i++) s += sh[i];
        tot = rsqrtf(s / n + 1e-6f);
    }
    __syncthreads();
    float rs = tot;
    bf16* hrow = hi + (size_t)blockIdx.x * n;
    bf16* lrow = lo + (size_t)blockIdx.x * n;
    for (int i = threadIdx.x; i < n; i += 256) {
        float y = row[i] * rs * w[i];
        bf16 h = __float2bfloat16(y);
        hrow[i] = h;
        lrow[i] = __float2bfloat16(y - __bfloat162float(h));
    }
}

// ---------------- gate alpha ----------------
__global__ __launch_bounds__(256) void alpha_kernel(
    const float* __restrict__ x, const float* __restrict__ wg,
    const float* __restrict__ bg, float* __restrict__ alpha,
    float* __restrict__ out_alpha)
{
    const float* row = x + (size_t)blockIdx.x * DD;
    float s = 0.f;
    for (int i = threadIdx.x; i < DD; i += 256) s += row[i] * wg[i];
    __shared__ float sh[8];
    int lane = threadIdx.x & 31, wp = threadIdx.x >> 5;
#pragma unroll
    for (int o = 16; o; o >>= 1) s += __shfl_xor_sync(0xffffffffu, s, o);
    if (lane == 0) sh[wp] = s;
    __syncthreads();
    if (threadIdx.x == 0) {
        float t = 0.f;
        for (int i = 0; i < 8; i++) t += sh[i];
        float z = t + bg[0];
        float a = 1.f / (1.f + expf(-z));
        alpha[blockIdx.x] = a;
        if (out_alpha) out_alpha[blockIdx.x] = a;
    }
}

// ---------------- assemble Q/K/V with EPE-RoPE (emit split bf16) -----------
__global__ __launch_bounds__(128) void assemble_kernel(
    const float* __restrict__ qc, const float* __restrict__ qr,
    const float* __restrict__ kc, const float* __restrict__ kr,
    const float* __restrict__ vv, const float* __restrict__ unc,
    bf16* __restrict__ Qh, bf16* __restrict__ Ql,
    bf16* __restrict__ Kh, bf16* __restrict__ Kl,
    bf16* __restrict__ Vh, bf16* __restrict__ Vl)
{
    int idx = blockIdx.x;
    int h  = idx % NHH;
    int bt = idx / NHH;
    int t  = bt % TT;
    int b  = bt / TT;
    __shared__ float cs[32], sn[32];
    int d = threadIdx.x;
    if (d < 32) {
        float u = unc[bt];
        u = fminf(fmaxf(u, 0.f), 1.f);
        float scale = 0.5f + 1.5f * u;
        float fi = (float)d / 32.0f;
        float theta = expf(-fi * logf(500000.0f));
        float fr = (float)t * theta * scale;
        cs[d] = cosf(fr);
        sn[d] = sinf(fr);
    }
    __syncthreads();
    size_t qkrow = ((size_t)(b*NHH + h))*TT + t;

    float qv0 = qc[(size_t)bt*2048 + h*128 + d];
    float kv0 = kc[(size_t)bt*2048 + h*128 + d];
    float vv0 = vv[(size_t)bt*2048 + h*128 + d];
    bf16 hh;
    hh = __float2bfloat16(qv0);
    Qh[qkrow*DQK + d] = hh; Ql[qkrow*DQK + d] = __float2bfloat16(qv0 - __bfloat162float(hh));
    hh = __float2bfloat16(kv0);
    Kh[qkrow*DQK + d] = hh; Kl[qkrow*DQK + d] = __float2bfloat16(kv0 - __bfloat162float(hh));
    hh = __float2bfloat16(vv0);
    Vh[qkrow*DVV + d] = hh; Vl[qkrow*DVV + d] = __float2bfloat16(vv0 - __bfloat162float(hh));

    if (d < 64) {
        const float* qrp = qr + (size_t)bt*1024 + h*64;
        const float* krp = kr + (size_t)bt*1024 + h*64;
        float qv, kv;
        if (d < 32) {
            float c = cs[d], s = sn[d];
            qv = qrp[d]*c - qrp[d+32]*s;
            kv = krp[d]*c - krp[d+32]*s;
        } else {
            int j = d - 32;
            float c = cs[j], s = sn[j];
            qv = qrp[j+32]*c + qrp[j]*s;
            kv = krp[j+32]*c + krp[j]*s;
        }
        hh = __float2bfloat16(qv);
        Qh[qkrow*DQK + 128 + d] = hh;
        Ql[qkrow*DQK + 128 + d] = __float2bfloat16(qv - __bfloat162float(hh));
        hh = __float2bfloat16(kv);
        Kh[qkrow*DQK + 128 + d] = hh;
        Kl[qkrow*DQK + 128 + d] = __float2bfloat16(kv - __bfloat162float(hh));
    }
}

// ---------------- tensor-core fused dual attention ----------------
// grid (T/64, B*NH), block 128 (4 warps). Warp w: query rows 16w..16w+15.
#define KSTR 200
#define VSTR 136
#define ATTN_SMEM ((64*KSTR*2 + 2*64*KSTR*2 + 2*64*VSTR*2) * 2)  // bytes

__global__ void __launch_bounds__(128, 1) attn_tc_kernel(
    const bf16* __restrict__ Qh, const bf16* __restrict__ Ql,
    const bf16* __restrict__ Kh, const bf16* __restrict__ Kl,
    const bf16* __restrict__ Vh, const bf16* __restrict__ Vl,
    const float* __restrict__ alpha,
    bf16* __restrict__ mgh, bf16* __restrict__ mgl)
{
    extern __shared__ __align__(16) bf16 smem[];
    bf16* sQh = smem;                  // 64*KSTR
    bf16* sQl = sQh + 64*KSTR;
    bf16* sKh = sQl + 64*KSTR;         // 2 bufs
    bf16* sKl = sKh + 2*64*KSTR;       // 2 bufs
    bf16* sVh = sKl + 2*64*KSTR;       // 2 bufs
    bf16* sVl = sVh + 2*64*VSTR;       // 2 bufs

    int tid = threadIdx.x, lane = tid & 31, warp = tid >> 5;
    int qt = blockIdx.x * 64;
    int bh = blockIdx.y;
    int b = bh >> 4, h = bh & 15;
    size_t base = (size_t)bh * TT;

    for (int i = tid; i < 64*24; i += 128) {
        int r = i / 24, c = (i % 24) * 8;
        size_t g = (base + qt + r) * DQK + c;
        cpa16(&sQh[r*KSTR + c], Qh + g);
        cpa16(&sQl[r*KSTR + c], Ql + g);
    }
    for (int i = tid; i < 64*24; i += 128) {
        int r = i / 24, c = (i % 24) * 8;
        size_t g = (base + r) * DQK + c;
        cpa16(&sKh[r*KSTR + c], Kh + g);
        cpa16(&sKl[r*KSTR + c], Kl + g);
    }
    for (int i = tid; i < 64*16; i += 128) {
        int r = i / 16, c = (i % 16) * 8;
        size_t g = (base + r) * DVV + c;
        cpa16(&sVh[r*VSTR + c], Vh + g);
        cpa16(&sVl[r*VSTR + c], Vl + g);
    }
    CP_COMMIT;

    int q0 = qt + 16*warp + (lane >> 2);
    int q1 = q0 + 8;
    int winlo = ((qt >> 8) << 8) - HALFW;
    if (winlo < 0) winlo = 0;

    float ob[16][4], ow[16][4];
#pragma unroll
    for (int n = 0; n < 16; n++)
#pragma unroll
        for (int j = 0; j < 4; j++) { ob[n][j] = 0.f; ow[n][j] = 0.f; }
    float m0 = -1e30f, m1 = -1e30f;
    float lb0 = 0.f, lb1 = 0.f, lw0 = 0.f, lw1 = 0.f;

    for (int t = 0; t < 32; t++) {
        int kt = t * 64;
        int nb = (t + 1) & 1;
        if (t + 1 < 32) {
            int kn = kt + 64;
            for (int i = tid; i < 64*24; i += 128) {
                int r = i / 24, c = (i % 24) * 8;
                size_t g = (base + kn + r) * DQK + c;
                cpa16(&sKh[nb*64*KSTR + r*KSTR + c], Kh + g);
                cpa16(&sKl[nb*64*KSTR + r*KSTR + c], Kl + g);
            }
            for (int i = tid; i < 64*16; i += 128) {
                int r = i / 16, c = (i % 16) * 8;
                size_t g = (base + kn + r) * DVV + c;
                cpa16(&sVh[nb*64*VSTR + r*VSTR + c], Vh + g);
                cpa16(&sVl[nb*64*VSTR + r*VSTR + c], Vl + g);
            }
        }
        CP_COMMIT;
        CP_WAIT1;
        __syncthreads();

        const bf16* bKh = sKh + (t & 1) * 64 * KSTR;
        const bf16* bVh = sVh + (t & 1) * 64 * VSTR;

        // ---- S = Q K^T (3 split chains) ----
        float sacc[8][4];
#pragma unroll
        for (int n = 0; n < 8; n++)
#pragma unroll
            for (int j = 0; j < 4; j++) sacc[n][j] = 0.f;

#pragma unroll
        for (int ks = 0; ks < 12; ks++) {
            uint32_t qhf[4], qlf[4];
            const bf16* ap = &sQh[(16*warp + (lane & 15))*KSTR + ks*16 + (lane >> 4)*8];
            ldsm_x4(qhf, ap);
            ldsm_x4(qlf, ap + 64*KSTR);
#pragma unroll
            for (int np = 0; np < 4; np++) {
                int g2 = lane >> 3;
                int krow = np*16 + (g2 >> 1)*8 + (lane & 7);
                int kcol = ks*16 + (g2 & 1)*8;
                const bf16* bp = &bKh[krow*KSTR + kcol];
                uint32_t khf[4], klf[4];
                ldsm_x4(khf, bp);
                ldsm_x4(klf, bp + 2*64*KSTR);
                mma_bf16(sacc[2*np],   qhf, khf);
                mma_bf16(sacc[2*np],   qhf, klf);
                mma_bf16(sacc[2*np],   qlf, khf);
                mma_bf16(sacc[2*np+1], qhf, khf + 2);
                mma_bf16(sacc[2*np+1], qhf, klf + 2);
                mma_bf16(sacc[2*np+1], qlf, khf + 2);
            }
        }

        // ---- online softmax ----
        float tm0 = -1e30f, tm1 = -1e30f;
#pragma unroll
        for (int n = 0; n < 8; n++) {
            tm0 = fmaxf(tm0, fmaxf(sacc[n][0], sacc[n][1]));
            tm1 = fmaxf(tm1, fmaxf(sacc[n][2], sacc[n][3]));
        }
        tm0 *= RSCALE; tm1 *= RSCALE;
        tm0 = fmaxf(tm0, __shfl_xor_sync(0xffffffffu, tm0, 1));
        tm0 = fmaxf(tm0, __shfl_xor_sync(0xffffffffu, tm0, 2));
        tm1 = fmaxf(tm1, __shfl_xor_sync(0xffffffffu, tm1, 1));
        tm1 = fmaxf(tm1, __shfl_xor_sync(0xffffffffu, tm1, 2));
        float mn0 = fmaxf(m0, tm0), mn1 = fmaxf(m1, tm1);
        float c0 = __expf(m0 - mn0), c1 = __expf(m1 - mn1);
        m0 = mn0; m1 = mn1;
        lb0 *= c0; lb1 *= c1; lw0 *= c0; lw1 *= c1;
        if (c0 < 1.f || c1 < 1.f) {
#pragma unroll
            for (int n = 0; n < 16; n++) {
                ob[n][0] *= c0; ob[n][1] *= c0; ob[n][2] *= c1; ob[n][3] *= c1;
                ow[n][0] *= c0; ow[n][1] *= c0; ow[n][2] *= c1; ow[n][3] *= c1;
            }
        }

        bool artile = (kt >= winlo) && (kt <= qt);
        float sb0 = 0.f, sb1 = 0.f, sw0 = 0.f, sw1 = 0.f;
#pragma unroll
        for (int n = 0; n < 8; n++) {
            float p0 = __expf(sacc[n][0]*RSCALE - mn0);
            float p1 = __expf(sacc[n][1]*RSCALE - mn0);
            float p2 = __expf(sacc[n][2]*RSCALE - mn1);
            float p3 = __expf(sacc[n][3]*RSCALE - mn1);
            sacc[n][0] = p0; sacc[n][1] = p1; sacc[n][2] = p2; sacc[n][3] = p3;
            sb0 += p0 + p1; sb1 += p2 + p3;
            if (artile) {
                int keyc = kt + 8*n + 2*(lane & 3);
                sw0 += ((keyc   <= q0) ? p0 : 0.f) + ((keyc+1 <= q0) ? p1 : 0.f);
                sw1 += ((keyc   <= q1) ? p2 : 0.f) + ((keyc+1 <= q1) ? p3 : 0.f);
            }
        }
        sb0 += __shfl_xor_sync(0xffffffffu, sb0, 1); sb0 += __shfl_xor_sync(0xffffffffu, sb0, 2);
        sb1 += __shfl_xor_sync(0xffffffffu, sb1, 1); sb1 += __shfl_xor_sync(0xffffffffu, sb1, 2);
        sw0 += __shfl_xor_sync(0xffffffffu, sw0, 1); sw0 += __shfl_xor_sync(0xffffffffu, sw0, 2);
        sw1 += __shfl_xor_sync(0xffffffffu, sw1, 1); sw1 += __shfl_xor_sync(0xffffffffu, sw1, 2);
        lb0 += sb0; lb1 += sb1; lw0 += sw0; lw1 += sw1;

        // ---- P V (bidir + windowed AR) ----
#pragma unroll
        for (int j = 0; j < 4; j++) {
            float v0 = sacc[2*j][0],   v1 = sacc[2*j][1];
            float v2 = sacc[2*j][2],   v3 = sacc[2*j][3];
            float v4 = sacc[2*j+1][0], v5 = sacc[2*j+1][1];
            float v6 = sacc[2*j+1][2], v7 = sacc[2*j+1][3];
            bf16 h0 = __float2bfloat16(v0), h1 = __float2bfloat16(v1);
            bf16 h2 = __float2bfloat16(v2), h3 = __float2bfloat16(v3);
            bf16 h4 = __float2bfloat16(v4), h5 = __float2bfloat16(v5);
            bf16 h6 = __float2bfloat16(v6), h7 = __float2bfloat16(v7);
            bf16 e0 = __float2bfloat16(v0 - __bfloat162float(h0));
            bf16 e1 = __float2bfloat16(v1 - __bfloat162float(h1));
            bf16 e2 = __float2bfloat16(v2 - __bfloat162float(h2));
            bf16 e3 = __float2bfloat16(v3 - __bfloat162float(h3));
            bf16 e4 = __float2bfloat16(v4 - __bfloat162float(h4));
            bf16 e5 = __float2bfloat16(v5 - __bfloat162float(h5));
            bf16 e6 = __float2bfloat16(v6 - __bfloat162float(h6));
            bf16 e7 = __float2bfloat16(v7 - __bfloat162float(h7));
            uint32_t ph[4] = { pk(h0,h1), pk(h2,h3), pk(h4,h5), pk(h6,h7) };
            uint32_t pl[4] = { pk(e0,e1), pk(e2,e3), pk(e4,e5), pk(e6,e7) };
            uint32_t wh[4], wl[4];
            if (artile) {
                bf16 z = __float2bfloat16(0.f);
                int kc = kt + 16*j + 2*(lane & 3);
                bool a0 = kc   <= q0, a1 = kc+1 <= q0;
                bool b0m = kc  <= q1, b1m = kc+1 <= q1;
                bool a2 = kc+8 <= q0, a3 = kc+9 <= q0;
                bool b2m = kc+8 <= q1, b3m = kc+9 <= q1;
                wh[0] = pk(a0?h0:z, a1?h1:z);  wl[0] = pk(a0?e0:z, a1?e1:z);
                wh[1] = pk(b0m?h2:z, b1m?h3:z); wl[1] = pk(b0m?e2:z, b1m?e3:z);
                wh[2] = pk(a2?h4:z, a3?h5:z);  wl[2] = pk(a2?e4:z, a3?e5:z);
                wh[3] = pk(b2m?h6:z, b3m?h7:z); wl[3] = pk(b2m?e6:z, b3m?e7:z);
            }
#pragma unroll
            for (int np = 0; np < 8; np++) {
                int g2 = lane >> 3;
                int vrow = 16*j + (g2 & 1)*8 + (lane & 7);
                int vcol = np*16 + (g2 >> 1)*8;
                const bf16* vp = &bVh[vrow*VSTR + vcol];
                uint32_t vhf[4], vlf[4];
                ldsm_x4t(vhf, vp);
                ldsm_x4t(vlf, vp + 2*64*VSTR);
                mma_bf16(ob[2*np],   ph, vhf);
                mma_bf16(ob[2*np],   ph, vlf);
                mma_bf16(ob[2*np],   pl, vhf);
                mma_bf16(ob[2*np+1], ph, vhf + 2);
                mma_bf16(ob[2*np+1], ph, vlf + 2);
                mma_bf16(ob[2*np+1], pl, vhf + 2);
                if (artile) {
                    mma_bf16(ow[2*np],   wh, vhf);
                    mma_bf16(ow[2*np],   wh, vlf);
                    mma_bf16(ow[2*np],   wl, vhf);
                    mma_bf16(ow[2*np+1], wh, vhf + 2);
                    mma_bf16(ow[2*np+1], wh, vlf + 2);
                    mma_bf16(ow[2*np+1], wl, vhf + 2);
                }
            }
        }
        __syncthreads();
    }

    // ---- epilogue: gate-merge, split-bf16 store ----
    float a0 = alpha[(size_t)b*TT + q0];
    float a1 = alpha[(size_t)b*TT + q1];
    float ilb0 = 1.f/lb0, ilb1 = 1.f/lb1, ilw0 = 1.f/lw0, ilw1 = 1.f/lw1;
    size_t r0o = ((size_t)b*TT + q0)*2048 + (size_t)h*128;
    size_t r1o = ((size_t)b*TT + q1)*2048 + (size_t)h*128;
#pragma unroll
    for (int n = 0; n < 16; n++) {
        int d = 8*n + 2*(lane & 3);
        float o00 = a0*ob[n][0]*ilb0 + (1.f-a0)*ow[n][0]*ilw0;
        float o01 = a0*ob[n][1]*ilb0 + (1.f-a0)*ow[n][1]*ilw0;
        float o10 = a1*ob[n][2]*ilb1 + (1.f-a1)*ow[n][2]*ilw1;
        float o11 = a1*ob[n][3]*ilb1 + (1.f-a1)*ow[n][3]*ilw1;
        bf16 h00 = __float2bfloat16(o00), h01 = __float2bfloat16(o01);
        bf16 h10 = __float2bfloat16(o10), h11 = __float2bfloat16(o11);
        *(uint32_t*)(mgh + r0o + d) = pk(h00, h01);
        *(uint32_t*)(mgh + r1o + d) = pk(h10, h11);
        *(uint32_t*)(mgl + r0o + d) = pk(
            __float2bfloat16(o00 - __bfloat162float(h00)),
            __float2bfloat16(o01 - __bfloat162float(h01)));
        *(uint32_t*)(mgl + r1o + d) = pk(
            __float2bfloat16(o10 - __bfloat162float(h10)),
            __float2bfloat16(o11 - __bfloat162float(h11)));
    }
}

// ---------------- launcher ----------------
extern "C" void kernel_launch(void* const* d_in, const int* in_sizes, int n_in,
                              void* d_out, int out_size)
{
    (void)in_sizes; (void)n_in;
    const float* x        = (const float*)d_in[0];
    const float* unc      = (const float*)d_in[1];
    const float* Wq_down  = (const float*)d_in[2];
    const float* q_norm_w = (const float*)d_in[3];
    const float* Wq_up    = (const float*)d_in[4];
    const float* Wq_rope  = (const float*)d_in[5];
    const float* Wkv_down = (const float*)d_in[6];
    const float* kv_norm_w= (const float*)d_in[7];
    const float* Wk_up    = (const float*)d_in[8];
    const float* Wv_up    = (const float*)d_in[9];
    const float* Wk_rope  = (const float*)d_in[10];
    const float* Wout     = (const float*)d_in[11];
    const float* Wgate    = (const float*)d_in[12];
    const float* bgate    = (const float*)d_in[13];
    float* out = (float*)d_out;

    float *qlat, *kvlat, *qc, *qr, *kc, *vv, *kr, *al;
    bf16 *Qh,*Ql,*Kh,*Kl,*Vh,*Vl;
    bf16 *xh,*xl,*qlh,*qll,*kvh,*kvl,*mgh,*mgl;
    bf16 *wqdh,*wqdl,*wquh,*wqul,*wqrh,*wqrl,*wkdh,*wkdl;
    bf16 *wkuh,*wkul,*wvuh,*wvul,*wkrh,*wkrl,*woh,*wol;
    cudaGetSymbolAddress((void**)&qlat,  g_qlat);
    cudaGetSymbolAddress((void**)&kvlat, g_kvlat);
    cudaGetSymbolAddress((void**)&qc,    g_qc);
    cudaGetSymbolAddress((void**)&qr,    g_qr);
    cudaGetSymbolAddress((void**)&kc,    g_kc);
    cudaGetSymbolAddress((void**)&vv,    g_vv);
    cudaGetSymbolAddress((void**)&kr,    g_kr);
    cudaGetSymbolAddress((void**)&al,    g_alpha);
    cudaGetSymbolAddress((void**)&Qh,    g_Qh);
    cudaGetSymbolAddress((void**)&Ql,    g_Ql);
    cudaGetSymbolAddress((void**)&Kh,    g_Kh);
    cudaGetSymbolAddress((void**)&Kl,    g_Kl);
    cudaGetSymbolAddress((void**)&Vh,    g_Vh);
    cudaGetSymbolAddress((void**)&Vl,    g_Vl);
    cudaGetSymbolAddress((void**)&xh,    g_xh);
    cudaGetSymbolAddress((void**)&xl,    g_xl);
    cudaGetSymbolAddress((void**)&qlh,   g_qlh);
    cudaGetSymbolAddress((void**)&qll,   g_qll);
    cudaGetSymbolAddress((void**)&kvh,   g_kvh);
    cudaGetSymbolAddress((void**)&kvl,   g_kvl);
    cudaGetSymbolAddress((void**)&mgh,   g_mgh);
    cudaGetSymbolAddress((void**)&mgl,   g_mgl);
    cudaGetSymbolAddress((void**)&wqdh,  g_wqd_h);
    cudaGetSymbolAddress((void**)&wqdl,  g_wqd_l);
    cudaGetSymbolAddress((void**)&wquh,  g_wqu_h);
    cudaGetSymbolAddress((void**)&wqul,  g_wqu_l);
    cudaGetSymbolAddress((void**)&wqrh,  g_wqr_h);
    cudaGetSymbolAddress((void**)&wqrl,  g_wqr_l);
    cudaGetSymbolAddress((void**)&wkdh,  g_wkd_h);
    cudaGetSymbolAddress((void**)&wkdl,  g_wkd_l);
    cudaGetSymbolAddress((void**)&wkuh,  g_wku_h);
    cudaGetSymbolAddress((void**)&wkul,  g_wku_l);
    cudaGetSymbolAddress((void**)&wvuh,  g_wvu_h);
    cudaGetSymbolAddress((void**)&wvul,  g_wvu_l);
    cudaGetSymbolAddress((void**)&wkrh,  g_wkr_h);
    cudaGetSymbolAddress((void**)&wkrl,  g_wkr_l);
    cudaGetSymbolAddress((void**)&woh,   g_wo_h);
    cudaGetSymbolAddress((void**)&wol,   g_wo_l);

    cudaFuncSetAttribute(attn_tc_kernel,
                         cudaFuncAttributeMaxDynamicSharedMemorySize, ATTN_SMEM);
    cudaFuncSetAttribute(gemm_split,
                         cudaFuncAttributeMaxDynamicSharedMemorySize, GS_SMEM);

    auto split = [&](const float* s, bf16* h, bf16* l, size_t n) {
        split_kernel<<<(int)(n / 1024), 256>>>(s, h, l, (int)n);
    };
    auto gemm = [&](const bf16* Ah, const bf16* Al, const bf16* Bh,
                    const bf16* Bl, float* C, int M, int N, int K) {
        gemm_split<<<dim3(N/128, M/128), 256, GS_SMEM>>>(Ah, Al, Bh, Bl, C, M, N, K);
    };

    split(x,        xh,   xl,   (size_t)BT*DD);
    split(Wq_down,  wqdh, wqdl, (size_t)DD*CQQ);
    split(Wq_up,    wquh, wqul, (size_t)CQQ*2048);
    split(Wq_rope,  wqrh, wqrl, (size_t)CQQ*1024);
    split(Wkv_down, wkdh, wkdl, (size_t)DD*CKVV);
    split(Wk_up,    wkuh, wkul, (size_t)CKVV*2048);
    split(Wv_up,    wvuh, wvul, (size_t)CKVV*2048);
    split(Wk_rope,  wkrh, wkrl, (size_t)DD*1024);
    split(Wout,     woh,  wol,  (size_t)2048*DD);

    gemm(xh, xl, wqdh, wqdl, qlat,  BT, CQQ,  DD);
    rmsnorm_split_kernel<<<BT, 256>>>(qlat, q_norm_w, qlh, qll, CQQ);
    gemm(xh, xl, wkdh, wkdl, kvlat, BT, CKVV, DD);
    rmsnorm_split_kernel<<<BT, 256>>>(kvlat, kv_norm_w, kvh, kvl, CKVV);

    gemm(qlh, qll, wquh, wqul, qc, BT, 2048, CQQ);
    gemm(qlh, qll, wqrh, wqrl, qr, BT, 1024, CQQ);
    gemm(kvh, kvl, wkuh, wkul, kc, BT, 2048, CKVV);
    gemm(kvh, kvl, wvuh, wvul, vv, BT, 2048, CKVV);
    gemm(xh, xl, wkrh, wkrl, kr, BT, 1024, DD);

    float* out_alpha = (out_size >= BB*TT*DD + BB*TT) ? (out + (size_t)BB*TT*DD)
                                                      : nullptr;
    alpha_kernel<<<BT, 256>>>(x, Wgate, bgate, al, out_alpha);

    assemble_kernel<<<BT*NHH, 128>>>(qc, qr, kc, kr, vv, unc,
                                     Qh, Ql, Kh, Kl, Vh, Vl);

    attn_tc_kernel<<<dim3(TT/64, BB*NHH), 128, ATTN_SMEM>>>(
        Qh, Ql, Kh, Kl, Vh, Vl, al, mgh, mgl);

    gemm(mgh, mgl, woh, wol, out, BT, DD, 2048);
}